// round 3
// baseline (speedup 1.0000x reference)
#include <cuda_runtime.h>
#include <math.h>

#define Dn   128
#define SQn  16
#define SKn  4096
#define BHn  64
#define TILE 128
#define NTHREADS 256
#define NBLOCKS  (BHn * (SKn / TILE))   /* 2048 */

/* device scratch (no allocation allowed) */
__device__ float g_Rt[Dn*Dn];     /* Rt[d][j] = R[j][d] */
__device__ float g_St[Dn*Dn];     /* St[d][m] = S[m][d] */
__device__ float g_qR[BHn*SQn*Dn];
__device__ float g_qS[BHn*SQn*Dn];

/* ---- prep 1: transposes ---- */
__global__ void prep1(const float* __restrict__ rot, const float* __restrict__ S)
{
    int j = blockIdx.x, t = threadIdx.x;       /* 128 x 128 */
    g_Rt[t*Dn + j] = rot[j*Dn + t];
    g_St[t*Dn + j] = S[j*Dn + t];
}

/* ---- prep 2: qR = Q @ R^T, qS = Q @ S^T per (b,h) (continuous, any order) ---- */
__global__ void prep_q(const float* __restrict__ query,
                       const float* __restrict__ rot,
                       const float* __restrict__ S)
{
    __shared__ float sq[SQn*Dn];
    int bh = blockIdx.x, t = threadIdx.x;      /* 64 x 256 */
    for (int i = t; i < SQn*Dn; i += NTHREADS) sq[i] = query[bh*SQn*Dn + i];
    __syncthreads();
#pragma unroll
    for (int c = 0; c < (SQn*Dn)/NTHREADS; ++c) {
        int o = t + c*NTHREADS;
        int q = o >> 7, j = o & 127;
        const float* qp = sq + q*Dn;
        const float* rp = rot + j*Dn;
        const float* sp = S   + j*Dn;
        float aR = 0.f, aS = 0.f;
#pragma unroll 8
        for (int d = 0; d < Dn; ++d) { float qq = qp[d]; aR = __fmaf_rn(qq, rp[d], aR); aS = __fmaf_rn(qq, sp[d], aS); }
        g_qR[bh*SQn*Dn + o] = aR;
        g_qS[bh*SQn*Dn + o] = aS;
    }
}

__device__ __forceinline__ float wsum(float v)
{
#pragma unroll
    for (int o = 16; o > 0; o >>= 1) v += __shfl_xor_sync(0xffffffffu, v, o);
    return v;
}
__device__ __forceinline__ double wsumd(double v)
{
#pragma unroll
    for (int o = 16; o > 0; o >>= 1) v += __shfl_xor_sync(0xffffffffu, v, o);
    return v;
}

/* ---- main fused kernel: one block = 128 keys of one (b,h) ----
 * Bit-mimics the reference fp32 dataflow for all DISCRETE decisions:
 *   k_hat = fl(k / n)                       (IEEE div on rounded fp32 norm)
 *   y_j   = seq-FMA chain over d of k_hat[d]*R[j][d]   -> quantize bins
 *   m_d   = seq-FMA chain over j of yhat[j]*R[j][d]
 *   km_d  = fl(m_d * n);  r_d = k_d - km_d  (explicit per-element rounding)
 *   r_hat = fl(r / rnorm)                   (IEEE div)
 *   proj_m= seq-FMA chain over d of r_hat[d]*S[m][d]   -> signs
 */
__global__ void __launch_bounds__(NTHREADS, 1)
turbo_main(const float* __restrict__ keys, const float* __restrict__ rot,
           const float* __restrict__ levels, float* __restrict__ out)
{
    extern __shared__ float sm[];
    float*  sM    = sm;                 /* 16384 B: Rt -> rot -> St  */
    float*  sK    = sM + Dn*Dn;         /* 65536 B: keys -> r_hat    */
    float*  sKh   = sK + TILE*Dn;       /* 65536 B: k_hat -> yhat    */
    float*  sQR   = sKh + TILE*Dn;      /*  2048 B                   */
    float*  sQS   = sQR + SQn*Dn;       /*  2048 B                   */
    float*  sNorm = sQS + SQn*Dn;       /*   512 B                   */
    float*  sRn   = sNorm + TILE;       /*   512 B                   */
    unsigned* sSign = (unsigned*)(sRn + TILE); /* 2048 B */

    const int tid = threadIdx.x, w = tid >> 5, lane = tid & 31;
    const int bh  = blockIdx.x >> 5;
    const int k0  = (blockIdx.x & 31) * TILE;

    /* cooperative loads */
    {
        const float4* g = (const float4*)(keys + ((size_t)bh*SKn + k0)*Dn);
        float4* s = (float4*)sK;
        for (int i = tid; i < TILE*Dn/4; i += NTHREADS) s[i] = g[i];
    }
    {
        const float4* g = (const float4*)g_Rt; float4* s = (float4*)sM;
        for (int i = tid; i < Dn*Dn/4; i += NTHREADS) s[i] = g[i];
    }
    {
        const float4* g = (const float4*)(g_qR + bh*SQn*Dn); float4* s = (float4*)sQR;
        for (int i = tid; i < SQn*Dn/4; i += NTHREADS) s[i] = g[i];
        g = (const float4*)(g_qS + bh*SQn*Dn); s = (float4*)sQS;
        for (int i = tid; i < SQn*Dn/4; i += NTHREADS) s[i] = g[i];
    }
    const float L0 = __ldg(levels+0), L1 = __ldg(levels+1),
                L2 = __ldg(levels+2), L3 = __ldg(levels+3);
    const float bb0 = 0.5f*(L0+L1), bb1 = 0.5f*(L1+L2), bb2 = 0.5f*(L2+L3);
    __syncthreads();

    /* norms: fp64 accumulate (best estimate of ref's tree-reduced fp32 norm) */
    for (int i = 0; i < 16; ++i) {
        int key = w*16 + i;
        float4 v = ((const float4*)(sK + key*Dn))[lane];
        double ss = (double)v.x*v.x + (double)v.y*v.y + (double)v.z*v.z + (double)v.w*v.w;
        ss = wsumd(ss);
        if (lane == 0) sNorm[key] = fmaxf((float)sqrt(ss), 1e-8f);
    }
    __syncthreads();

    /* k_hat = fl(k / n): IEEE round-to-nearest division, like the reference */
    for (int i = tid; i < TILE*Dn; i += NTHREADS)
        sKh[i] = __fdiv_rn(sK[i], sNorm[i >> 7]);
    __syncthreads();

    /* ===== phase 1: y = k_hat @ R^T via sequential FMA chain; quantize ===== */
    for (int cc = 0; cc < 4; ++cc) {
        const int kb = w*16 + cc*4;
        const float* kp[4];
#pragma unroll
        for (int i = 0; i < 4; ++i) kp[i] = sKh + (kb+i)*Dn;
        float4 a[4];
#pragma unroll
        for (int i = 0; i < 4; ++i) a[i] = make_float4(0.f,0.f,0.f,0.f);
#pragma unroll 4
        for (int d = 0; d < Dn; ++d) {
            float4 r = ((const float4*)sM)[d*32 + lane];
#pragma unroll
            for (int i = 0; i < 4; ++i) {
                float x = kp[i][d];
                a[i].x = __fmaf_rn(x, r.x, a[i].x);
                a[i].y = __fmaf_rn(x, r.y, a[i].y);
                a[i].z = __fmaf_rn(x, r.z, a[i].z);
                a[i].w = __fmaf_rn(x, r.w, a[i].w);
            }
        }
        /* quantize -> yhat, overwrite k_hat rows (own keys only, reads done) */
#pragma unroll
        for (int i = 0; i < 4; ++i) {
            float4 yh;
            { float y = a[i].x; yh.x = y > bb1 ? (y > bb2 ? L3 : L2) : (y > bb0 ? L1 : L0); }
            { float y = a[i].y; yh.y = y > bb1 ? (y > bb2 ? L3 : L2) : (y > bb0 ? L1 : L0); }
            { float y = a[i].z; yh.z = y > bb1 ? (y > bb2 ? L3 : L2) : (y > bb0 ? L1 : L0); }
            { float y = a[i].w; yh.w = y > bb1 ? (y > bb2 ? L3 : L2) : (y > bb0 ? L1 : L0); }
            ((float4*)(sKh + (kb+i)*Dn))[lane] = yh;
        }
    }
    __syncthreads();

    /* reload matrix slot with R itself (row-major rot[j][d]) */
    {
        const float4* g = (const float4*)rot; float4* s = (float4*)sM;
        for (int i = tid; i < Dn*Dn/4; i += NTHREADS) s[i] = g[i];
    }
    __syncthreads();

    /* ===== phase 2: keys_mse = fl(fl(yhat@R) * n); residual; r_hat ===== */
    for (int cc = 0; cc < 4; ++cc) {
        const int kb = w*16 + cc*4;
        const float* yp[4];
#pragma unroll
        for (int i = 0; i < 4; ++i) yp[i] = sKh + (kb+i)*Dn;
        float4 a[4];
#pragma unroll
        for (int i = 0; i < 4; ++i) a[i] = make_float4(0.f,0.f,0.f,0.f);
#pragma unroll 4
        for (int j = 0; j < Dn; ++j) {
            float4 r = ((const float4*)sM)[j*32 + lane];
#pragma unroll
            for (int i = 0; i < 4; ++i) {
                float x = yp[i][j];
                a[i].x = __fmaf_rn(x, r.x, a[i].x);
                a[i].y = __fmaf_rn(x, r.y, a[i].y);
                a[i].z = __fmaf_rn(x, r.z, a[i].z);
                a[i].w = __fmaf_rn(x, r.w, a[i].w);
            }
        }
#pragma unroll
        for (int i = 0; i < 4; ++i) {
            int key = kb + i;
            float n = sNorm[key];
            float4 kv = ((const float4*)(sK + key*Dn))[lane];
            /* explicit rounding: km = fl(m*n); r = fl(k - km) */
            float4 r;
            r.x = __fadd_rn(kv.x, -__fmul_rn(a[i].x, n));
            r.y = __fadd_rn(kv.y, -__fmul_rn(a[i].y, n));
            r.z = __fadd_rn(kv.z, -__fmul_rn(a[i].z, n));
            r.w = __fadd_rn(kv.w, -__fmul_rn(a[i].w, n));
            double ss = (double)r.x*r.x + (double)r.y*r.y + (double)r.z*r.z + (double)r.w*r.w;
            ss = wsumd(ss);
            float rn = fmaxf((float)sqrt(ss), 1e-10f);
            if (lane == 0) sRn[key] = rn;
            float4 rh;
            rh.x = __fdiv_rn(r.x, rn);
            rh.y = __fdiv_rn(r.y, rn);
            rh.z = __fdiv_rn(r.z, rn);
            rh.w = __fdiv_rn(r.w, rn);
            ((float4*)(sK + key*Dn))[lane] = rh;   /* overwrite keys with r_hat */
        }
    }
    __syncthreads();

    /* reload matrix slot: St[d][m] */
    {
        const float4* g = (const float4*)g_St; float4* s = (float4*)sM;
        for (int i = tid; i < Dn*Dn/4; i += NTHREADS) s[i] = g[i];
    }
    __syncthreads();

    /* ===== phase 3: proj = r_hat @ S^T via sequential FMA chain; signs ===== */
    for (int cc = 0; cc < 4; ++cc) {
        const int kb = w*16 + cc*4;
        const float* rp[4];
#pragma unroll
        for (int i = 0; i < 4; ++i) rp[i] = sK + (kb+i)*Dn;
        float4 a[4];
#pragma unroll
        for (int i = 0; i < 4; ++i) a[i] = make_float4(0.f,0.f,0.f,0.f);
#pragma unroll 4
        for (int d = 0; d < Dn; ++d) {
            float4 t = ((const float4*)sM)[d*32 + lane];
#pragma unroll
            for (int i = 0; i < 4; ++i) {
                float x = rp[i][d];
                a[i].x = __fmaf_rn(x, t.x, a[i].x);
                a[i].y = __fmaf_rn(x, t.y, a[i].y);
                a[i].z = __fmaf_rn(x, t.z, a[i].z);
                a[i].w = __fmaf_rn(x, t.w, a[i].w);
            }
        }
#pragma unroll
        for (int i = 0; i < 4; ++i) {
            unsigned b0 = __ballot_sync(0xffffffffu, a[i].x >= 0.f);
            unsigned b1 = __ballot_sync(0xffffffffu, a[i].y >= 0.f);
            unsigned b2 = __ballot_sync(0xffffffffu, a[i].z >= 0.f);
            unsigned b3 = __ballot_sync(0xffffffffu, a[i].w >= 0.f);
            if (lane == 0) {
                unsigned* sp = sSign + (size_t)(kb+i)*4;
                sp[0]=b0; sp[1]=b1; sp[2]=b2; sp[3]=b3;
            }
        }
    }
    __syncthreads();

    /* ===== epilogue: out = n*(qR.yhat) + c*rnorm*(qS.sign) (continuous) ===== */
    const float cq = 0.0097915167f;   /* sqrt(pi/2)/128 */
    float* og = out + ((size_t)bh*SQn)*SKn + k0;
    for (int p = 0; p < 256; ++p) {
        int pair = w*256 + p;
        int q = pair >> 7, key = pair & 127;
        float4 yv = ((const float4*)(sKh + key*Dn))[lane];
        float4 qr = ((const float4*)(sQR + q*Dn))[lane];
        float4 qs = ((const float4*)(sQS + q*Dn))[lane];
        const unsigned* sp = sSign + (size_t)key*4;
        unsigned w0 = sp[0], w1 = sp[1], w2 = sp[2], w3 = sp[3];
        unsigned bit = 1u << lane;
        float sE = yv.x*qr.x + yv.y*qr.y + yv.z*qr.z + yv.w*qr.w;
        float sS = ((w0 & bit) ? qs.x : -qs.x) + ((w1 & bit) ? qs.y : -qs.y)
                 + ((w2 & bit) ? qs.z : -qs.z) + ((w3 & bit) ? qs.w : -qs.w);
        sE = wsum(sE);
        sS = wsum(sS);
        if (lane == 0)
            og[(size_t)q*SKn + key] = sNorm[key]*sE + cq*sRn[key]*sS;
    }
}

extern "C" void kernel_launch(void* const* d_in, const int* in_sizes, int n_in,
                              void* d_out, int out_size)
{
    const float* query  = (const float*)d_in[0];
    const float* keys   = (const float*)d_in[1];
    const float* rot    = (const float*)d_in[2];
    const float* S      = (const float*)d_in[3];
    const float* levels = (const float*)d_in[4];
    float* out = (float*)d_out;

    const int SMEM = (Dn*Dn + 2*TILE*Dn + 2*SQn*Dn + 2*TILE) * 4 + TILE*4*4; /* 154624 B */
    cudaFuncSetAttribute(turbo_main, cudaFuncAttributeMaxDynamicSharedMemorySize, SMEM);

    prep1<<<Dn, Dn>>>(rot, S);
    prep_q<<<BHn, NTHREADS>>>(query, rot, S);
    turbo_main<<<NBLOCKS, NTHREADS, SMEM>>>(keys, rot, levels, out);
}

// round 4
// speedup vs baseline: 1.3710x; 1.3710x over previous
#include <cuda_runtime.h>
#include <math.h>

#define Dn   128
#define SQn  16
#define SKn  4096
#define BHn  64
#define TILE 128
#define NTHREADS 512
#define NWARPS   (NTHREADS/32)
#define NBLOCKS  (BHn * (SKn / TILE))   /* 2048 */

/* device scratch (no allocation allowed) */
__device__ float g_Rt[Dn*Dn];     /* Rt[d][j] = R[j][d] */
__device__ float g_St[Dn*Dn];     /* St[d][m] = S[m][d] */
__device__ float g_qR[BHn*SQn*Dn];
__device__ float g_qS[BHn*SQn*Dn];

/* ---- prep 1: transposes ---- */
__global__ void prep1(const float* __restrict__ rot, const float* __restrict__ S)
{
    int j = blockIdx.x, t = threadIdx.x;       /* 128 x 128 */
    g_Rt[t*Dn + j] = rot[j*Dn + t];
    g_St[t*Dn + j] = S[j*Dn + t];
}

/* ---- prep 2: qR = Q @ R^T, qS = Q @ S^T per (b,h) (continuous) ---- */
__global__ void prep_q(const float* __restrict__ query,
                       const float* __restrict__ rot,
                       const float* __restrict__ S)
{
    __shared__ float sq[SQn*Dn];
    int bh = blockIdx.x, t = threadIdx.x;      /* 64 x 256 */
    for (int i = t; i < SQn*Dn; i += 256) sq[i] = query[bh*SQn*Dn + i];
    __syncthreads();
#pragma unroll
    for (int c = 0; c < (SQn*Dn)/256; ++c) {
        int o = t + c*256;
        int q = o >> 7, j = o & 127;
        const float* qp = sq + q*Dn;
        const float* rp = rot + j*Dn;
        const float* sp = S   + j*Dn;
        float aR = 0.f, aS = 0.f;
#pragma unroll 8
        for (int d = 0; d < Dn; ++d) { float qq = qp[d]; aR = __fmaf_rn(qq, rp[d], aR); aS = __fmaf_rn(qq, sp[d], aS); }
        g_qR[bh*SQn*Dn + o] = aR;
        g_qS[bh*SQn*Dn + o] = aS;
    }
}

__device__ __forceinline__ float wsum(float v)
{
#pragma unroll
    for (int o = 16; o > 0; o >>= 1) v += __shfl_xor_sync(0xffffffffu, v, o);
    return v;
}
__device__ __forceinline__ double wsumd(double v)
{
#pragma unroll
    for (int o = 16; o > 0; o >>= 1) v += __shfl_xor_sync(0xffffffffu, v, o);
    return v;
}

/* core: 4 keys x 4 outputs-per-lane matvec step, operands vectorized over d.
 * Accumulation order over d is UNCHANGED (bit-identical to scalar version). */
#define MV_BODY(SRC0,SRC1,SRC2,SRC3)                                          \
    _Pragma("unroll 2")                                                       \
    for (int db = 0; db < Dn; db += 4) {                                      \
        float4 x0 = *(const float4*)(SRC0 + db);                              \
        float4 x1 = *(const float4*)(SRC1 + db);                              \
        float4 x2 = *(const float4*)(SRC2 + db);                              \
        float4 x3 = *(const float4*)(SRC3 + db);                              \
        float xs0[4] = {x0.x,x0.y,x0.z,x0.w};                                 \
        float xs1[4] = {x1.x,x1.y,x1.z,x1.w};                                 \
        float xs2[4] = {x2.x,x2.y,x2.z,x2.w};                                 \
        float xs3[4] = {x3.x,x3.y,x3.z,x3.w};                                 \
        _Pragma("unroll")                                                     \
        for (int dd = 0; dd < 4; ++dd) {                                      \
            float4 r = ((const float4*)sM)[(db+dd)*32 + lane];                \
            float x;                                                          \
            x = xs0[dd];                                                      \
            a[0].x = __fmaf_rn(x, r.x, a[0].x);                               \
            a[0].y = __fmaf_rn(x, r.y, a[0].y);                               \
            a[0].z = __fmaf_rn(x, r.z, a[0].z);                               \
            a[0].w = __fmaf_rn(x, r.w, a[0].w);                               \
            x = xs1[dd];                                                      \
            a[1].x = __fmaf_rn(x, r.x, a[1].x);                               \
            a[1].y = __fmaf_rn(x, r.y, a[1].y);                               \
            a[1].z = __fmaf_rn(x, r.z, a[1].z);                               \
            a[1].w = __fmaf_rn(x, r.w, a[1].w);                               \
            x = xs2[dd];                                                      \
            a[2].x = __fmaf_rn(x, r.x, a[2].x);                               \
            a[2].y = __fmaf_rn(x, r.y, a[2].y);                               \
            a[2].z = __fmaf_rn(x, r.z, a[2].z);                               \
            a[2].w = __fmaf_rn(x, r.w, a[2].w);                               \
            x = xs3[dd];                                                      \
            a[3].x = __fmaf_rn(x, r.x, a[3].x);                               \
            a[3].y = __fmaf_rn(x, r.y, a[3].y);                               \
            a[3].z = __fmaf_rn(x, r.z, a[3].z);                               \
            a[3].w = __fmaf_rn(x, r.w, a[3].w);                               \
        }                                                                     \
    }

/* ---- main fused kernel: one block = 128 keys of one (b,h), 16 warps ---- */
__global__ void __launch_bounds__(NTHREADS, 1)
turbo_main(const float* __restrict__ keys, const float* __restrict__ rot,
           const float* __restrict__ levels, float* __restrict__ out)
{
    extern __shared__ float sm[];
    float*  sM    = sm;                 /* 16384 B: Rt -> rot -> St  */
    float*  sK    = sM + Dn*Dn;         /* 65536 B: keys -> r_hat    */
    float*  sKh   = sK + TILE*Dn;       /* 65536 B: k_hat -> yhat    */
    float*  sQR   = sKh + TILE*Dn;      /*  2048 B                   */
    float*  sQS   = sQR + SQn*Dn;       /*  2048 B                   */
    float*  sNorm = sQS + SQn*Dn;       /*   512 B                   */
    float*  sRn   = sNorm + TILE;       /*   512 B                   */
    unsigned* sSign = (unsigned*)(sRn + TILE); /* 2048 B */

    const int tid = threadIdx.x, w = tid >> 5, lane = tid & 31;
    const int bh  = blockIdx.x >> 5;
    const int k0  = (blockIdx.x & 31) * TILE;

    /* cooperative loads */
    {
        const float4* g = (const float4*)(keys + ((size_t)bh*SKn + k0)*Dn);
        float4* s = (float4*)sK;
        for (int i = tid; i < TILE*Dn/4; i += NTHREADS) s[i] = g[i];
    }
    {
        const float4* g = (const float4*)g_Rt; float4* s = (float4*)sM;
        for (int i = tid; i < Dn*Dn/4; i += NTHREADS) s[i] = g[i];
    }
    {
        const float4* g = (const float4*)(g_qR + bh*SQn*Dn); float4* s = (float4*)sQR;
        for (int i = tid; i < SQn*Dn/4; i += NTHREADS) s[i] = g[i];
        g = (const float4*)(g_qS + bh*SQn*Dn); s = (float4*)sQS;
        for (int i = tid; i < SQn*Dn/4; i += NTHREADS) s[i] = g[i];
    }
    const float L0 = __ldg(levels+0), L1 = __ldg(levels+1),
                L2 = __ldg(levels+2), L3 = __ldg(levels+3);
    const float bb0 = 0.5f*(L0+L1), bb1 = 0.5f*(L1+L2), bb2 = 0.5f*(L2+L3);
    __syncthreads();

    /* norms: fp64 accumulate; each warp owns 8 keys */
#pragma unroll
    for (int i = 0; i < 8; ++i) {
        int key = w*8 + i;
        float4 v = ((const float4*)(sK + key*Dn))[lane];
        double ss = (double)v.x*v.x + (double)v.y*v.y + (double)v.z*v.z + (double)v.w*v.w;
        ss = wsumd(ss);
        if (lane == 0) sNorm[key] = fmaxf((float)sqrt(ss), 1e-8f);
    }
    __syncthreads();

    /* k_hat = fl(k / n): IEEE round-to-nearest division */
    for (int i = tid; i < TILE*Dn; i += NTHREADS)
        sKh[i] = __fdiv_rn(sK[i], sNorm[i >> 7]);
    __syncthreads();

    /* ===== phase 1: y = k_hat @ R^T (seq FMA over d); quantize ===== */
#pragma unroll
    for (int cc = 0; cc < 2; ++cc) {
        const int kb = w*8 + cc*4;
        const float* p0 = sKh + (kb+0)*Dn;
        const float* p1 = sKh + (kb+1)*Dn;
        const float* p2 = sKh + (kb+2)*Dn;
        const float* p3 = sKh + (kb+3)*Dn;
        float4 a[4];
#pragma unroll
        for (int i = 0; i < 4; ++i) a[i] = make_float4(0.f,0.f,0.f,0.f);
        MV_BODY(p0,p1,p2,p3)
        /* quantize -> yhat, overwrite k_hat rows (own keys, reads done) */
#pragma unroll
        for (int i = 0; i < 4; ++i) {
            float4 yh;
            { float y = a[i].x; yh.x = y > bb1 ? (y > bb2 ? L3 : L2) : (y > bb0 ? L1 : L0); }
            { float y = a[i].y; yh.y = y > bb1 ? (y > bb2 ? L3 : L2) : (y > bb0 ? L1 : L0); }
            { float y = a[i].z; yh.z = y > bb1 ? (y > bb2 ? L3 : L2) : (y > bb0 ? L1 : L0); }
            { float y = a[i].w; yh.w = y > bb1 ? (y > bb2 ? L3 : L2) : (y > bb0 ? L1 : L0); }
            ((float4*)(sKh + (kb+i)*Dn))[lane] = yh;
        }
    }
    __syncthreads();

    /* reload matrix slot with R itself (row-major rot[j][d]) */
    {
        const float4* g = (const float4*)rot; float4* s = (float4*)sM;
        for (int i = tid; i < Dn*Dn/4; i += NTHREADS) s[i] = g[i];
    }
    __syncthreads();

    /* ===== phase 2: keys_mse = fl(fl(yhat@R)*n); residual; r_hat ===== */
#pragma unroll
    for (int cc = 0; cc < 2; ++cc) {
        const int kb = w*8 + cc*4;
        const float* p0 = sKh + (kb+0)*Dn;
        const float* p1 = sKh + (kb+1)*Dn;
        const float* p2 = sKh + (kb+2)*Dn;
        const float* p3 = sKh + (kb+3)*Dn;
        float4 a[4];
#pragma unroll
        for (int i = 0; i < 4; ++i) a[i] = make_float4(0.f,0.f,0.f,0.f);
        MV_BODY(p0,p1,p2,p3)
#pragma unroll
        for (int i = 0; i < 4; ++i) {
            int key = kb + i;
            float n = sNorm[key];
            float4 kv = ((const float4*)(sK + key*Dn))[lane];
            float4 r;
            r.x = __fadd_rn(kv.x, -__fmul_rn(a[i].x, n));
            r.y = __fadd_rn(kv.y, -__fmul_rn(a[i].y, n));
            r.z = __fadd_rn(kv.z, -__fmul_rn(a[i].z, n));
            r.w = __fadd_rn(kv.w, -__fmul_rn(a[i].w, n));
            double ss = (double)r.x*r.x + (double)r.y*r.y + (double)r.z*r.z + (double)r.w*r.w;
            ss = wsumd(ss);
            float rn = fmaxf((float)sqrt(ss), 1e-10f);
            if (lane == 0) sRn[key] = rn;
            float4 rh;
            rh.x = __fdiv_rn(r.x, rn);
            rh.y = __fdiv_rn(r.y, rn);
            rh.z = __fdiv_rn(r.z, rn);
            rh.w = __fdiv_rn(r.w, rn);
            ((float4*)(sK + key*Dn))[lane] = rh;   /* overwrite keys with r_hat */
        }
    }
    __syncthreads();

    /* reload matrix slot: St[d][m] */
    {
        const float4* g = (const float4*)g_St; float4* s = (float4*)sM;
        for (int i = tid; i < Dn*Dn/4; i += NTHREADS) s[i] = g[i];
    }
    __syncthreads();

    /* ===== phase 3: proj = r_hat @ S^T (seq FMA over d); signs ===== */
#pragma unroll
    for (int cc = 0; cc < 2; ++cc) {
        const int kb = w*8 + cc*4;
        const float* p0 = sK + (kb+0)*Dn;
        const float* p1 = sK + (kb+1)*Dn;
        const float* p2 = sK + (kb+2)*Dn;
        const float* p3 = sK + (kb+3)*Dn;
        float4 a[4];
#pragma unroll
        for (int i = 0; i < 4; ++i) a[i] = make_float4(0.f,0.f,0.f,0.f);
        MV_BODY(p0,p1,p2,p3)
#pragma unroll
        for (int i = 0; i < 4; ++i) {
            unsigned b0 = __ballot_sync(0xffffffffu, a[i].x >= 0.f);
            unsigned b1 = __ballot_sync(0xffffffffu, a[i].y >= 0.f);
            unsigned b2 = __ballot_sync(0xffffffffu, a[i].z >= 0.f);
            unsigned b3 = __ballot_sync(0xffffffffu, a[i].w >= 0.f);
            if (lane == 0) {
                unsigned* sp = sSign + (size_t)(kb+i)*4;
                sp[0]=b0; sp[1]=b1; sp[2]=b2; sp[3]=b3;
            }
        }
    }
    __syncthreads();

    /* ===== epilogue: out = n*(qR.yhat) + c*rnorm*(qS.sign) ===== */
    const float cq = 0.0097915167f;   /* sqrt(pi/2)/128 */
    float* og = out + ((size_t)bh*SQn)*SKn + k0;
#pragma unroll 2
    for (int p = 0; p < 2048/NWARPS; ++p) {
        int pair = w*(2048/NWARPS) + p;
        int q = pair >> 7, key = pair & 127;
        float4 yv = ((const float4*)(sKh + key*Dn))[lane];
        float4 qr = ((const float4*)(sQR + q*Dn))[lane];
        float4 qs = ((const float4*)(sQS + q*Dn))[lane];
        const unsigned* sp = sSign + (size_t)key*4;
        unsigned w0 = sp[0], w1 = sp[1], w2 = sp[2], w3 = sp[3];
        unsigned bit = 1u << lane;
        float sE = yv.x*qr.x + yv.y*qr.y + yv.z*qr.z + yv.w*qr.w;
        float sS = ((w0 & bit) ? qs.x : -qs.x) + ((w1 & bit) ? qs.y : -qs.y)
                 + ((w2 & bit) ? qs.z : -qs.z) + ((w3 & bit) ? qs.w : -qs.w);
        sE = wsum(sE);
        sS = wsum(sS);
        if (lane == 0)
            og[(size_t)q*SKn + key] = sNorm[key]*sE + cq*sRn[key]*sS;
    }
}

extern "C" void kernel_launch(void* const* d_in, const int* in_sizes, int n_in,
                              void* d_out, int out_size)
{
    const float* query  = (const float*)d_in[0];
    const float* keys   = (const float*)d_in[1];
    const float* rot    = (const float*)d_in[2];
    const float* S      = (const float*)d_in[3];
    const float* levels = (const float*)d_in[4];
    float* out = (float*)d_out;

    const int SMEM = (Dn*Dn + 2*TILE*Dn + 2*SQn*Dn + 2*TILE) * 4 + TILE*4*4; /* 154624 B */
    cudaFuncSetAttribute(turbo_main, cudaFuncAttributeMaxDynamicSharedMemorySize, SMEM);

    prep1<<<Dn, Dn>>>(rot, S);
    prep_q<<<BHn, 256>>>(query, rot, S);
    turbo_main<<<NBLOCKS, NTHREADS, SMEM>>>(keys, rot, levels, out);
}

// round 5
// speedup vs baseline: 1.4152x; 1.0322x over previous
#include <cuda_runtime.h>
#include <math.h>

#define Dn   128
#define SQn  16
#define SKn  4096
#define BHn  64
#define TILE 64
#define NTHREADS 256
#define NWARPS   8
#define NBLOCKS  (BHn * (SKn / TILE))   /* 4096 */

/* device scratch (no allocation allowed) */
__device__ float g_Rt[Dn*Dn];     /* Rt[d][j] = R[j][d] */
__device__ float g_St[Dn*Dn];     /* St[d][m] = S[m][d] */
__device__ float g_qR[BHn*SQn*Dn];
__device__ float g_qS[BHn*SQn*Dn];

/* ---- prep 1: transposes ---- */
__global__ void prep1(const float* __restrict__ rot, const float* __restrict__ S)
{
    int j = blockIdx.x, t = threadIdx.x;       /* 128 x 128 */
    g_Rt[t*Dn + j] = rot[j*Dn + t];
    g_St[t*Dn + j] = S[j*Dn + t];
}

/* ---- prep 2: qR = Q @ R^T, qS = Q @ S^T per (b,h) (continuous) ---- */
__global__ void prep_q(const float* __restrict__ query,
                       const float* __restrict__ rot,
                       const float* __restrict__ S)
{
    __shared__ float sq[SQn*Dn];
    int bh = blockIdx.x, t = threadIdx.x;      /* 64 x 256 */
    for (int i = t; i < SQn*Dn; i += 256) sq[i] = query[bh*SQn*Dn + i];
    __syncthreads();
#pragma unroll
    for (int c = 0; c < (SQn*Dn)/256; ++c) {
        int o = t + c*256;
        int q = o >> 7, j = o & 127;
        const float* qp = sq + q*Dn;
        const float* rp = rot + j*Dn;
        const float* sp = S   + j*Dn;
        float aR = 0.f, aS = 0.f;
#pragma unroll 8
        for (int d = 0; d < Dn; ++d) { float qq = qp[d]; aR = __fmaf_rn(qq, rp[d], aR); aS = __fmaf_rn(qq, sp[d], aS); }
        g_qR[bh*SQn*Dn + o] = aR;
        g_qS[bh*SQn*Dn + o] = aS;
    }
}

__device__ __forceinline__ float wsum(float v)
{
#pragma unroll
    for (int o = 16; o > 0; o >>= 1) v += __shfl_xor_sync(0xffffffffu, v, o);
    return v;
}

/* 16-FMA core step: 4 keys x float4 outputs, one matrix float4 per dd */
#define FMA16(XD0,XD1,XD2,XD3,RV)                                   \
    {                                                               \
        float x;                                                    \
        x = XD0;                                                    \
        a[0].x = __fmaf_rn(x, RV.x, a[0].x);                        \
        a[0].y = __fmaf_rn(x, RV.y, a[0].y);                        \
        a[0].z = __fmaf_rn(x, RV.z, a[0].z);                        \
        a[0].w = __fmaf_rn(x, RV.w, a[0].w);                        \
        x = XD1;                                                    \
        a[1].x = __fmaf_rn(x, RV.x, a[1].x);                        \
        a[1].y = __fmaf_rn(x, RV.y, a[1].y);                        \
        a[1].z = __fmaf_rn(x, RV.z, a[1].z);                        \
        a[1].w = __fmaf_rn(x, RV.w, a[1].w);                        \
        x = XD2;                                                    \
        a[2].x = __fmaf_rn(x, RV.x, a[2].x);                        \
        a[2].y = __fmaf_rn(x, RV.y, a[2].y);                        \
        a[2].z = __fmaf_rn(x, RV.z, a[2].z);                        \
        a[2].w = __fmaf_rn(x, RV.w, a[2].w);                        \
        x = XD3;                                                    \
        a[3].x = __fmaf_rn(x, RV.x, a[3].x);                        \
        a[3].y = __fmaf_rn(x, RV.y, a[3].y);                        \
        a[3].z = __fmaf_rn(x, RV.z, a[3].z);                        \
        a[3].w = __fmaf_rn(x, RV.w, a[3].w);                        \
    }

/* smem-row operand matvec: operands broadcast float4 from sSrc rows */
#define MV_ROWS(P0,P1,P2,P3,MAT)                                    \
    _Pragma("unroll 2")                                             \
    for (int db = 0; db < Dn; db += 4) {                            \
        float4 x0 = *(const float4*)((P0) + db);                    \
        float4 x1 = *(const float4*)((P1) + db);                    \
        float4 x2 = *(const float4*)((P2) + db);                    \
        float4 x3 = *(const float4*)((P3) + db);                    \
        float xs0[4] = {x0.x,x0.y,x0.z,x0.w};                       \
        float xs1[4] = {x1.x,x1.y,x1.z,x1.w};                       \
        float xs2[4] = {x2.x,x2.y,x2.z,x2.w};                       \
        float xs3[4] = {x3.x,x3.y,x3.z,x3.w};                       \
        _Pragma("unroll")                                           \
        for (int dd = 0; dd < 4; ++dd) {                            \
            float4 r = ((const float4*)(MAT))[(db+dd)*32 + lane];   \
            FMA16(xs0[dd],xs1[dd],xs2[dd],xs3[dd],r)                \
        }                                                           \
    }

/* ---- main fused kernel: one block = 64 keys of one (b,h), 8 warps ---- */
__global__ void __launch_bounds__(NTHREADS, 3)
turbo_main(const float* __restrict__ keys, const float* __restrict__ rot,
           const float* __restrict__ levels, float* __restrict__ out)
{
    __shared__ float  sM[Dn*Dn];        /* 16K: Rt -> rot -> St  */
    __shared__ float  sK[TILE*Dn];      /* 32K: keys -> k_hat -> r_hat */
    __shared__ float  sQR[SQn*Dn];      /*  8K */
    __shared__ float  sQS[SQn*Dn];      /*  8K */
    __shared__ float  sTab[256*4];      /*  4K: byte -> 4 level values */
    __shared__ float  sNorm[TILE];
    __shared__ float  sRn[TILE];
    __shared__ unsigned sSign[TILE*4];  /*  1K */
    __shared__ unsigned char sCodeB[TILE*32]; /* 2K: 2-bit yhat codes */

    const int tid = threadIdx.x, w = tid >> 5, lane = tid & 31;
    const int bh  = blockIdx.x >> 6;            /* 64 tiles per bh */
    const int k0  = (blockIdx.x & 63) * TILE;
    const float* keys_blk = keys + ((size_t)bh*SKn + k0)*Dn;

    const float L0 = __ldg(levels+0), L1 = __ldg(levels+1),
                L2 = __ldg(levels+2), L3 = __ldg(levels+3);
    const float bb0 = 0.5f*(L0+L1), bb1 = 0.5f*(L1+L2), bb2 = 0.5f*(L2+L3);

    /* cooperative loads */
    {
        const float4* g = (const float4*)keys_blk;
        float4* s = (float4*)sK;
#pragma unroll
        for (int i = tid; i < TILE*Dn/4; i += NTHREADS) s[i] = g[i];
    }
    {
        const float4* g = (const float4*)g_Rt; float4* s = (float4*)sM;
#pragma unroll
        for (int i = tid; i < Dn*Dn/4; i += NTHREADS) s[i] = g[i];
    }
    {
        const float4* g = (const float4*)(g_qR + bh*SQn*Dn); float4* s = (float4*)sQR;
#pragma unroll
        for (int i = tid; i < SQn*Dn/4; i += NTHREADS) s[i] = g[i];
        g = (const float4*)(g_qS + bh*SQn*Dn); s = (float4*)sQS;
#pragma unroll
        for (int i = tid; i < SQn*Dn/4; i += NTHREADS) s[i] = g[i];
    }
    /* byte -> float4 level decode table (exact level values) */
    {
        unsigned b = tid;                       /* 256 threads = 256 bytes */
        float v[4];
#pragma unroll
        for (int c = 0; c < 4; ++c) {
            unsigned cc = (b >> (2*c)) & 3u;
            float lo = (cc & 1u) ? L1 : L0;
            float hi = (cc & 1u) ? L3 : L2;
            v[c] = (cc & 2u) ? hi : lo;
        }
        ((float4*)sTab)[b] = make_float4(v[0],v[1],v[2],v[3]);
    }
    __syncthreads();

    /* norms (fp32, deterministic order); each warp owns 8 keys */
#pragma unroll
    for (int i = 0; i < 8; ++i) {
        int key = w*8 + i;
        float4 v = ((const float4*)(sK + key*Dn))[lane];
        float ss = __fmul_rn(v.x, v.x);
        ss = __fmaf_rn(v.y, v.y, ss);
        ss = __fmaf_rn(v.z, v.z, ss);
        ss = __fmaf_rn(v.w, v.w, ss);
        ss = wsum(ss);
        if (lane == 0) sNorm[key] = fmaxf(__fsqrt_rn(ss), 1e-8f);
    }
    __syncthreads();

    /* k_hat = fl(k / n) in place (IEEE div) */
#pragma unroll
    for (int i = tid; i < TILE*Dn; i += NTHREADS)
        sK[i] = __fdiv_rn(sK[i], sNorm[i >> 7]);
    __syncthreads();

    /* ===== phase 1: y = k_hat @ R^T (seq FMA over d); 2-bit codes ===== */
#pragma unroll
    for (int cc = 0; cc < 2; ++cc) {
        const int kb = w*8 + cc*4;
        const float* p0 = sK + (kb+0)*Dn;
        const float* p1 = sK + (kb+1)*Dn;
        const float* p2 = sK + (kb+2)*Dn;
        const float* p3 = sK + (kb+3)*Dn;
        float4 a[4];
#pragma unroll
        for (int i = 0; i < 4; ++i) a[i] = make_float4(0.f,0.f,0.f,0.f);
        MV_ROWS(p0,p1,p2,p3,sM)
#pragma unroll
        for (int i = 0; i < 4; ++i) {
            unsigned c0, c1, c2, c3;
            { float y = a[i].x; c0 = (unsigned)(y > bb0) + (unsigned)(y > bb1) + (unsigned)(y > bb2); }
            { float y = a[i].y; c1 = (unsigned)(y > bb0) + (unsigned)(y > bb1) + (unsigned)(y > bb2); }
            { float y = a[i].z; c2 = (unsigned)(y > bb0) + (unsigned)(y > bb1) + (unsigned)(y > bb2); }
            { float y = a[i].w; c3 = (unsigned)(y > bb0) + (unsigned)(y > bb1) + (unsigned)(y > bb2); }
            sCodeB[(kb+i)*32 + lane] = (unsigned char)(c0 | (c1<<2) | (c2<<4) | (c3<<6));
        }
    }
    __syncthreads();

    /* reload matrix slot with R itself (row-major rot[j][d]) */
    {
        const float4* g = (const float4*)rot; float4* s = (float4*)sM;
#pragma unroll
        for (int i = tid; i < Dn*Dn/4; i += NTHREADS) s[i] = g[i];
    }
    __syncthreads();

    /* ===== phase 2: keys_mse = fl(fl(yhat@R)*n); residual; r_hat ===== */
#pragma unroll
    for (int cc = 0; cc < 2; ++cc) {
        const int kb = w*8 + cc*4;
        /* prefetch raw keys from global (L2) — hidden under the matvec */
        float4 kg[4];
#pragma unroll
        for (int i = 0; i < 4; ++i)
            kg[i] = ((const float4*)(keys_blk + (size_t)(kb+i)*Dn))[lane];

        const unsigned char* c0 = sCodeB + (kb+0)*32;
        const unsigned char* c1 = sCodeB + (kb+1)*32;
        const unsigned char* c2 = sCodeB + (kb+2)*32;
        const unsigned char* c3 = sCodeB + (kb+3)*32;
        float4 a[4];
#pragma unroll
        for (int i = 0; i < 4; ++i) a[i] = make_float4(0.f,0.f,0.f,0.f);
#pragma unroll 2
        for (int g = 0; g < 32; ++g) {          /* j = 4g..4g+3 */
            float4 x0 = ((const float4*)sTab)[c0[g]];
            float4 x1 = ((const float4*)sTab)[c1[g]];
            float4 x2 = ((const float4*)sTab)[c2[g]];
            float4 x3 = ((const float4*)sTab)[c3[g]];
            float xs0[4] = {x0.x,x0.y,x0.z,x0.w};
            float xs1[4] = {x1.x,x1.y,x1.z,x1.w};
            float xs2[4] = {x2.x,x2.y,x2.z,x2.w};
            float xs3[4] = {x3.x,x3.y,x3.z,x3.w};
#pragma unroll
            for (int dd = 0; dd < 4; ++dd) {
                float4 r = ((const float4*)sM)[(4*g+dd)*32 + lane];
                FMA16(xs0[dd],xs1[dd],xs2[dd],xs3[dd],r)
            }
        }
#pragma unroll
        for (int i = 0; i < 4; ++i) {
            int key = kb + i;
            float n = sNorm[key];
            float4 r;
            r.x = __fadd_rn(kg[i].x, -__fmul_rn(a[i].x, n));
            r.y = __fadd_rn(kg[i].y, -__fmul_rn(a[i].y, n));
            r.z = __fadd_rn(kg[i].z, -__fmul_rn(a[i].z, n));
            r.w = __fadd_rn(kg[i].w, -__fmul_rn(a[i].w, n));
            float ss = __fmul_rn(r.x, r.x);
            ss = __fmaf_rn(r.y, r.y, ss);
            ss = __fmaf_rn(r.z, r.z, ss);
            ss = __fmaf_rn(r.w, r.w, ss);
            ss = wsum(ss);
            float rn = fmaxf(__fsqrt_rn(ss), 1e-10f);
            if (lane == 0) sRn[key] = rn;
            float4 rh;
            rh.x = __fdiv_rn(r.x, rn);
            rh.y = __fdiv_rn(r.y, rn);
            rh.z = __fdiv_rn(r.z, rn);
            rh.w = __fdiv_rn(r.w, rn);
            ((float4*)(sK + key*Dn))[lane] = rh;   /* k_hat -> r_hat */
        }
    }
    __syncthreads();

    /* reload matrix slot: St[d][m] */
    {
        const float4* g = (const float4*)g_St; float4* s = (float4*)sM;
#pragma unroll
        for (int i = tid; i < Dn*Dn/4; i += NTHREADS) s[i] = g[i];
    }
    __syncthreads();

    /* ===== phase 3: proj = r_hat @ S^T (seq FMA over d); signs ===== */
#pragma unroll
    for (int cc = 0; cc < 2; ++cc) {
        const int kb = w*8 + cc*4;
        const float* p0 = sK + (kb+0)*Dn;
        const float* p1 = sK + (kb+1)*Dn;
        const float* p2 = sK + (kb+2)*Dn;
        const float* p3 = sK + (kb+3)*Dn;
        float4 a[4];
#pragma unroll
        for (int i = 0; i < 4; ++i) a[i] = make_float4(0.f,0.f,0.f,0.f);
        MV_ROWS(p0,p1,p2,p3,sM)
#pragma unroll
        for (int i = 0; i < 4; ++i) {
            unsigned b0 = __ballot_sync(0xffffffffu, a[i].x >= 0.f);
            unsigned b1 = __ballot_sync(0xffffffffu, a[i].y >= 0.f);
            unsigned b2 = __ballot_sync(0xffffffffu, a[i].z >= 0.f);
            unsigned b3 = __ballot_sync(0xffffffffu, a[i].w >= 0.f);
            if (lane == 0) {
                unsigned* sp = sSign + (size_t)(kb+i)*4;
                sp[0]=b0; sp[1]=b1; sp[2]=b2; sp[3]=b3;
            }
        }
    }
    __syncthreads();

    /* ===== epilogue: out = n*(qR.yhat) + c*rnorm*(qS.sign) ===== */
    const float cq = 0.0097915167f;   /* sqrt(pi/2)/128 */
    float* og = out + ((size_t)bh*SQn)*SKn + k0;
#pragma unroll 2
    for (int p = 0; p < (SQn*TILE)/NWARPS; ++p) {
        int pair = w*((SQn*TILE)/NWARPS) + p;
        int q = pair >> 6, key = pair & 63;
        unsigned byte = sCodeB[key*32 + lane];
        float4 yv = ((const float4*)sTab)[byte];
        float4 qr = ((const float4*)(sQR + q*Dn))[lane];
        float4 qs = ((const float4*)(sQS + q*Dn))[lane];
        const unsigned* sp = sSign + (size_t)key*4;
        unsigned w0 = sp[0], w1 = sp[1], w2 = sp[2], w3 = sp[3];
        unsigned bit = 1u << lane;
        float sE = yv.x*qr.x + yv.y*qr.y + yv.z*qr.z + yv.w*qr.w;
        float sS = ((w0 & bit) ? qs.x : -qs.x) + ((w1 & bit) ? qs.y : -qs.y)
                 + ((w2 & bit) ? qs.z : -qs.z) + ((w3 & bit) ? qs.w : -qs.w);
        sE = wsum(sE);
        sS = wsum(sS);
        if (lane == 0)
            og[(size_t)q*SKn + key] = sNorm[key]*sE + cq*sRn[key]*sS;
    }
}

extern "C" void kernel_launch(void* const* d_in, const int* in_sizes, int n_in,
                              void* d_out, int out_size)
{
    const float* query  = (const float*)d_in[0];
    const float* keys   = (const float*)d_in[1];
    const float* rot    = (const float*)d_in[2];
    const float* S      = (const float*)d_in[3];
    const float* levels = (const float*)d_in[4];
    float* out = (float*)d_out;

    prep1<<<Dn, Dn>>>(rot, S);
    prep_q<<<BHn, 256>>>(query, rot, S);
    turbo_main<<<NBLOCKS, NTHREADS>>>(keys, rot, levels, out);
}

// round 6
// speedup vs baseline: 2.0367x; 1.4391x over previous
#include <cuda_runtime.h>
#include <math.h>

#define Dn   128
#define SQn  16
#define SKn  4096
#define BHn  64
#define TILE 64
#define NTHREADS 256
#define NWARPS   8
#define NBLOCKS  (BHn * (SKn / TILE))   /* 4096 */

/* device scratch (no allocation allowed) */
__device__ float g_Rt[Dn*Dn];     /* Rt[d][j] = R[j][d] */
__device__ float g_St[Dn*Dn];     /* St[d][m] = S[m][d] */
__device__ float g_qR[BHn*SQn*Dn];
__device__ float g_qS[BHn*SQn*Dn];

/* ---- merged prep: transposes + qR/qS (one kernel -> 2-kernel period) ---- */
__global__ void prep_all(const float* __restrict__ query,
                         const float* __restrict__ rot,
                         const float* __restrict__ S)
{
    int j = blockIdx.x, t = threadIdx.x;       /* 128 x 128 */
    g_Rt[t*Dn + j] = rot[j*Dn + t];
    g_St[t*Dn + j] = S[j*Dn + t];

    if (blockIdx.x < BHn) {                    /* blocks 0..63 also do qR/qS */
        int bh = blockIdx.x;
        const float* qbase = query + (size_t)bh*SQn*Dn;
#pragma unroll
        for (int c = 0; c < (SQn*Dn)/128; ++c) {
            int o = t + c*128;
            int q = o >> 7, jj = o & 127;
            const float* qp = qbase + q*Dn;
            const float* rp = rot + jj*Dn;
            const float* sp = S   + jj*Dn;
            float aR = 0.f, aS = 0.f;
#pragma unroll 8
            for (int d = 0; d < Dn; ++d) {
                float qq = __ldg(qp + d);
                aR = __fmaf_rn(qq, __ldg(rp + d), aR);
                aS = __fmaf_rn(qq, __ldg(sp + d), aS);
            }
            g_qR[bh*SQn*Dn + o] = aR;
            g_qS[bh*SQn*Dn + o] = aS;
        }
    }
}

__device__ __forceinline__ float wsum(float v)
{
#pragma unroll
    for (int o = 16; o > 0; o >>= 1) v += __shfl_xor_sync(0xffffffffu, v, o);
    return v;
}

/* 16-FMA core step: 4 keys x float4 outputs, one matrix float4 per dd */
#define FMA16(XD0,XD1,XD2,XD3,RV)                                   \
    {                                                               \
        float x;                                                    \
        x = XD0;                                                    \
        a[0].x = __fmaf_rn(x, RV.x, a[0].x);                        \
        a[0].y = __fmaf_rn(x, RV.y, a[0].y);                        \
        a[0].z = __fmaf_rn(x, RV.z, a[0].z);                        \
        a[0].w = __fmaf_rn(x, RV.w, a[0].w);                        \
        x = XD1;                                                    \
        a[1].x = __fmaf_rn(x, RV.x, a[1].x);                        \
        a[1].y = __fmaf_rn(x, RV.y, a[1].y);                        \
        a[1].z = __fmaf_rn(x, RV.z, a[1].z);                        \
        a[1].w = __fmaf_rn(x, RV.w, a[1].w);                        \
        x = XD2;                                                    \
        a[2].x = __fmaf_rn(x, RV.x, a[2].x);                        \
        a[2].y = __fmaf_rn(x, RV.y, a[2].y);                        \
        a[2].z = __fmaf_rn(x, RV.z, a[2].z);                        \
        a[2].w = __fmaf_rn(x, RV.w, a[2].w);                        \
        x = XD3;                                                    \
        a[3].x = __fmaf_rn(x, RV.x, a[3].x);                        \
        a[3].y = __fmaf_rn(x, RV.y, a[3].y);                        \
        a[3].z = __fmaf_rn(x, RV.z, a[3].z);                        \
        a[3].w = __fmaf_rn(x, RV.w, a[3].w);                        \
    }

/* smem-row operand matvec: operands broadcast float4 from rows */
#define MV_ROWS(P0,P1,P2,P3,MAT)                                    \
    _Pragma("unroll 4")                                             \
    for (int db = 0; db < Dn; db += 4) {                            \
        float4 x0 = *(const float4*)((P0) + db);                    \
        float4 x1 = *(const float4*)((P1) + db);                    \
        float4 x2 = *(const float4*)((P2) + db);                    \
        float4 x3 = *(const float4*)((P3) + db);                    \
        float xs0[4] = {x0.x,x0.y,x0.z,x0.w};                       \
        float xs1[4] = {x1.x,x1.y,x1.z,x1.w};                       \
        float xs2[4] = {x2.x,x2.y,x2.z,x2.w};                       \
        float xs3[4] = {x3.x,x3.y,x3.z,x3.w};                       \
        _Pragma("unroll")                                           \
        for (int dd = 0; dd < 4; ++dd) {                            \
            float4 r = ((const float4*)(MAT))[(db+dd)*32 + lane];   \
            FMA16(xs0[dd],xs1[dd],xs2[dd],xs3[dd],r)                \
        }                                                           \
    }

/* ---- main fused kernel: one block = 64 keys of one (b,h), 8 warps ---- */
__global__ void __launch_bounds__(NTHREADS, 3)
turbo_main(const float* __restrict__ keys, const float* __restrict__ rot,
           const float* __restrict__ levels, float* __restrict__ out)
{
    __shared__ float  sM[Dn*Dn];        /* 16K: Rt -> rot -> St  */
    __shared__ float  sK[TILE*Dn];      /* 32K: keys -> k_hat -> r_hat */
    __shared__ float  sQR[SQn*Dn];      /*  8K */
    __shared__ float  sQS[SQn*Dn];      /*  8K */
    __shared__ float  sTab[256*4];      /*  4K: byte -> 4 level values */
    __shared__ float  sNorm[TILE];
    __shared__ float  sRn[TILE];
    __shared__ unsigned sSign[TILE*4];  /*  1K: bit L of word c = sign(m=4L+c) */
    __shared__ unsigned char sCodeB[TILE*32]; /* 2K: 2-bit yhat codes */

    const int tid = threadIdx.x, w = tid >> 5, lane = tid & 31;
    const int bh  = blockIdx.x >> 6;            /* 64 tiles per bh */
    const int k0  = (blockIdx.x & 63) * TILE;
    const float* keys_blk = keys + ((size_t)bh*SKn + k0)*Dn;

    const float L0 = __ldg(levels+0), L1 = __ldg(levels+1),
                L2 = __ldg(levels+2), L3 = __ldg(levels+3);
    const float bb0 = 0.5f*(L0+L1), bb1 = 0.5f*(L1+L2), bb2 = 0.5f*(L2+L3);

    /* cooperative loads */
    {
        const float4* g = (const float4*)keys_blk;
        float4* s = (float4*)sK;
#pragma unroll
        for (int i = tid; i < TILE*Dn/4; i += NTHREADS) s[i] = g[i];
    }
    {
        const float4* g = (const float4*)g_Rt; float4* s = (float4*)sM;
#pragma unroll
        for (int i = tid; i < Dn*Dn/4; i += NTHREADS) s[i] = g[i];
    }
    {
        const float4* g = (const float4*)(g_qR + bh*SQn*Dn); float4* s = (float4*)sQR;
#pragma unroll
        for (int i = tid; i < SQn*Dn/4; i += NTHREADS) s[i] = g[i];
        g = (const float4*)(g_qS + bh*SQn*Dn); s = (float4*)sQS;
#pragma unroll
        for (int i = tid; i < SQn*Dn/4; i += NTHREADS) s[i] = g[i];
    }
    /* byte -> float4 level decode table (exact level values) */
    {
        unsigned b = tid;
        float v[4];
#pragma unroll
        for (int c = 0; c < 4; ++c) {
            unsigned cc = (b >> (2*c)) & 3u;
            float lo = (cc & 1u) ? L1 : L0;
            float hi = (cc & 1u) ? L3 : L2;
            v[c] = (cc & 2u) ? hi : lo;
        }
        ((float4*)sTab)[b] = make_float4(v[0],v[1],v[2],v[3]);
    }
    __syncthreads();

    /* norms (fp32, deterministic order); each warp owns 8 keys */
#pragma unroll
    for (int i = 0; i < 8; ++i) {
        int key = w*8 + i;
        float4 v = ((const float4*)(sK + key*Dn))[lane];
        float ss = __fmul_rn(v.x, v.x);
        ss = __fmaf_rn(v.y, v.y, ss);
        ss = __fmaf_rn(v.z, v.z, ss);
        ss = __fmaf_rn(v.w, v.w, ss);
        ss = wsum(ss);
        if (lane == 0) sNorm[key] = fmaxf(__fsqrt_rn(ss), 1e-8f);
    }
    __syncthreads();

    /* k_hat = fl(k / n) in place (IEEE div) */
#pragma unroll
    for (int i = tid; i < TILE*Dn; i += NTHREADS)
        sK[i] = __fdiv_rn(sK[i], sNorm[i >> 7]);
    __syncthreads();

    /* ===== phase 1: y = k_hat @ R^T (seq FMA over d); 2-bit codes ===== */
#pragma unroll
    for (int cc = 0; cc < 2; ++cc) {
        const int kb = w*8 + cc*4;
        const float* p0 = sK + (kb+0)*Dn;
        const float* p1 = sK + (kb+1)*Dn;
        const float* p2 = sK + (kb+2)*Dn;
        const float* p3 = sK + (kb+3)*Dn;
        float4 a[4];
#pragma unroll
        for (int i = 0; i < 4; ++i) a[i] = make_float4(0.f,0.f,0.f,0.f);
        MV_ROWS(p0,p1,p2,p3,sM)
#pragma unroll
        for (int i = 0; i < 4; ++i) {
            unsigned c0, c1, c2, c3;
            { float y = a[i].x; c0 = (unsigned)(y > bb0) + (unsigned)(y > bb1) + (unsigned)(y > bb2); }
            { float y = a[i].y; c1 = (unsigned)(y > bb0) + (unsigned)(y > bb1) + (unsigned)(y > bb2); }
            { float y = a[i].z; c2 = (unsigned)(y > bb0) + (unsigned)(y > bb1) + (unsigned)(y > bb2); }
            { float y = a[i].w; c3 = (unsigned)(y > bb0) + (unsigned)(y > bb1) + (unsigned)(y > bb2); }
            sCodeB[(kb+i)*32 + lane] = (unsigned char)(c0 | (c1<<2) | (c2<<4) | (c3<<6));
        }
    }
    __syncthreads();

    /* reload matrix slot with R itself (row-major rot[j][d]) */
    {
        const float4* g = (const float4*)rot; float4* s = (float4*)sM;
#pragma unroll
        for (int i = tid; i < Dn*Dn/4; i += NTHREADS) s[i] = g[i];
    }
    __syncthreads();

    /* ===== phase 2: keys_mse = fl(fl(yhat@R)*n); residual; r_hat ===== */
#pragma unroll
    for (int cc = 0; cc < 2; ++cc) {
        const int kb = w*8 + cc*4;
        float4 kg[4];
#pragma unroll
        for (int i = 0; i < 4; ++i)
            kg[i] = ((const float4*)(keys_blk + (size_t)(kb+i)*Dn))[lane];

        const unsigned char* c0 = sCodeB + (kb+0)*32;
        const unsigned char* c1 = sCodeB + (kb+1)*32;
        const unsigned char* c2 = sCodeB + (kb+2)*32;
        const unsigned char* c3 = sCodeB + (kb+3)*32;
        float4 a[4];
#pragma unroll
        for (int i = 0; i < 4; ++i) a[i] = make_float4(0.f,0.f,0.f,0.f);
#pragma unroll 4
        for (int g = 0; g < 32; ++g) {          /* j = 4g..4g+3 */
            float4 x0 = ((const float4*)sTab)[c0[g]];
            float4 x1 = ((const float4*)sTab)[c1[g]];
            float4 x2 = ((const float4*)sTab)[c2[g]];
            float4 x3 = ((const float4*)sTab)[c3[g]];
            float xs0[4] = {x0.x,x0.y,x0.z,x0.w};
            float xs1[4] = {x1.x,x1.y,x1.z,x1.w};
            float xs2[4] = {x2.x,x2.y,x2.z,x2.w};
            float xs3[4] = {x3.x,x3.y,x3.z,x3.w};
#pragma unroll
            for (int dd = 0; dd < 4; ++dd) {
                float4 r = ((const float4*)sM)[(4*g+dd)*32 + lane];
                FMA16(xs0[dd],xs1[dd],xs2[dd],xs3[dd],r)
            }
        }
#pragma unroll
        for (int i = 0; i < 4; ++i) {
            int key = kb + i;
            float n = sNorm[key];
            float4 r;
            r.x = __fadd_rn(kg[i].x, -__fmul_rn(a[i].x, n));
            r.y = __fadd_rn(kg[i].y, -__fmul_rn(a[i].y, n));
            r.z = __fadd_rn(kg[i].z, -__fmul_rn(a[i].z, n));
            r.w = __fadd_rn(kg[i].w, -__fmul_rn(a[i].w, n));
            float ss = __fmul_rn(r.x, r.x);
            ss = __fmaf_rn(r.y, r.y, ss);
            ss = __fmaf_rn(r.z, r.z, ss);
            ss = __fmaf_rn(r.w, r.w, ss);
            ss = wsum(ss);
            float rn = fmaxf(__fsqrt_rn(ss), 1e-10f);
            if (lane == 0) sRn[key] = rn;
            float4 rh;
            rh.x = __fdiv_rn(r.x, rn);
            rh.y = __fdiv_rn(r.y, rn);
            rh.z = __fdiv_rn(r.z, rn);
            rh.w = __fdiv_rn(r.w, rn);
            ((float4*)(sK + key*Dn))[lane] = rh;   /* k_hat -> r_hat */
        }
    }
    __syncthreads();

    /* reload matrix slot: St[d][m] */
    {
        const float4* g = (const float4*)g_St; float4* s = (float4*)sM;
#pragma unroll
        for (int i = tid; i < Dn*Dn/4; i += NTHREADS) s[i] = g[i];
    }
    __syncthreads();

    /* ===== phase 3: proj = r_hat @ S^T (seq FMA over d); signs ===== */
#pragma unroll
    for (int cc = 0; cc < 2; ++cc) {
        const int kb = w*8 + cc*4;
        const float* p0 = sK + (kb+0)*Dn;
        const float* p1 = sK + (kb+1)*Dn;
        const float* p2 = sK + (kb+2)*Dn;
        const float* p3 = sK + (kb+3)*Dn;
        float4 a[4];
#pragma unroll
        for (int i = 0; i < 4; ++i) a[i] = make_float4(0.f,0.f,0.f,0.f);
        MV_ROWS(p0,p1,p2,p3,sM)
#pragma unroll
        for (int i = 0; i < 4; ++i) {
            unsigned b0 = __ballot_sync(0xffffffffu, a[i].x >= 0.f);
            unsigned b1 = __ballot_sync(0xffffffffu, a[i].y >= 0.f);
            unsigned b2 = __ballot_sync(0xffffffffu, a[i].z >= 0.f);
            unsigned b3 = __ballot_sync(0xffffffffu, a[i].w >= 0.f);
            if (lane == 0) {
                unsigned* sp = sSign + (size_t)(kb+i)*4;
                sp[0]=b0; sp[1]=b1; sp[2]=b2; sp[3]=b3;
            }
        }
    }
    __syncthreads();

    /* ===== epilogue (shfl-free): warp -> 2 q rows, lane -> keys {lane, lane+32}
       out = n*(qR.yhat) + cq*rnorm*(qS.sign) ===== */
    {
        const float cq = 0.0097915167f;   /* sqrt(pi/2)/128 */
        const int q0 = 2*w, q1 = 2*w + 1;
        const int kA = lane, kB = lane + 32;
        const float* qr0 = sQR + q0*Dn;
        const float* qr1 = sQR + q1*Dn;
        const float* qs0 = sQS + q0*Dn;
        const float* qs1 = sQS + q1*Dn;
        const unsigned char* cA = sCodeB + kA*32;
        const unsigned char* cB = sCodeB + kB*32;

        float e00 = 0.f, e01 = 0.f, e10 = 0.f, e11 = 0.f;  /* e[q][key] */
#pragma unroll 4
        for (int g = 0; g < 32; ++g) {
            float4 a0 = ((const float4*)qr0)[g];
            float4 a1 = ((const float4*)qr1)[g];
            float4 yA = ((const float4*)sTab)[cA[g]];
            float4 yB = ((const float4*)sTab)[cB[g]];
            e00 = __fmaf_rn(a0.x, yA.x, e00); e00 = __fmaf_rn(a0.y, yA.y, e00);
            e00 = __fmaf_rn(a0.z, yA.z, e00); e00 = __fmaf_rn(a0.w, yA.w, e00);
            e01 = __fmaf_rn(a0.x, yB.x, e01); e01 = __fmaf_rn(a0.y, yB.y, e01);
            e01 = __fmaf_rn(a0.z, yB.z, e01); e01 = __fmaf_rn(a0.w, yB.w, e01);
            e10 = __fmaf_rn(a1.x, yA.x, e10); e10 = __fmaf_rn(a1.y, yA.y, e10);
            e10 = __fmaf_rn(a1.z, yA.z, e10); e10 = __fmaf_rn(a1.w, yA.w, e10);
            e11 = __fmaf_rn(a1.x, yB.x, e11); e11 = __fmaf_rn(a1.y, yB.y, e11);
            e11 = __fmaf_rn(a1.z, yB.z, e11); e11 = __fmaf_rn(a1.w, yB.w, e11);
        }

        unsigned wA0 = sSign[kA*4+0], wA1 = sSign[kA*4+1],
                 wA2 = sSign[kA*4+2], wA3 = sSign[kA*4+3];
        unsigned wB0 = sSign[kB*4+0], wB1 = sSign[kB*4+1],
                 wB2 = sSign[kB*4+2], wB3 = sSign[kB*4+3];

        float s00 = 0.f, s01 = 0.f, s10 = 0.f, s11 = 0.f;  /* s[q][key] */
#pragma unroll 4
        for (int g = 0; g < 32; ++g) {        /* m = 4g + c, bit g of word c */
            float4 b0 = ((const float4*)qs0)[g];
            float4 b1 = ((const float4*)qs1)[g];
            float fA0 = ((wA0 >> g) & 1u) ? 1.f : -1.f;
            float fA1 = ((wA1 >> g) & 1u) ? 1.f : -1.f;
            float fA2 = ((wA2 >> g) & 1u) ? 1.f : -1.f;
            float fA3 = ((wA3 >> g) & 1u) ? 1.f : -1.f;
            float fB0 = ((wB0 >> g) & 1u) ? 1.f : -1.f;
            float fB1 = ((wB1 >> g) & 1u) ? 1.f : -1.f;
            float fB2 = ((wB2 >> g) & 1u) ? 1.f : -1.f;
            float fB3 = ((wB3 >> g) & 1u) ? 1.f : -1.f;
            s00 = __fmaf_rn(fA0, b0.x, s00); s00 = __fmaf_rn(fA1, b0.y, s00);
            s00 = __fmaf_rn(fA2, b0.z, s00); s00 = __fmaf_rn(fA3, b0.w, s00);
            s01 = __fmaf_rn(fB0, b0.x, s01); s01 = __fmaf_rn(fB1, b0.y, s01);
            s01 = __fmaf_rn(fB2, b0.z, s01); s01 = __fmaf_rn(fB3, b0.w, s01);
            s10 = __fmaf_rn(fA0, b1.x, s10); s10 = __fmaf_rn(fA1, b1.y, s10);
            s10 = __fmaf_rn(fA2, b1.z, s10); s10 = __fmaf_rn(fA3, b1.w, s10);
            s11 = __fmaf_rn(fB0, b1.x, s11); s11 = __fmaf_rn(fB1, b1.y, s11);
            s11 = __fmaf_rn(fB2, b1.z, s11); s11 = __fmaf_rn(fB3, b1.w, s11);
        }

        float nA = sNorm[kA], nB = sNorm[kB];
        float gA = cq * sRn[kA], gB = cq * sRn[kB];
        float* og = out + ((size_t)bh*SQn)*SKn + k0;
        og[(size_t)q0*SKn + kA] = nA*e00 + gA*s00;
        og[(size_t)q0*SKn + kB] = nB*e01 + gB*s01;
        og[(size_t)q1*SKn + kA] = nA*e10 + gA*s10;
        og[(size_t)q1*SKn + kB] = nB*e11 + gB*s11;
    }
}

extern "C" void kernel_launch(void* const* d_in, const int* in_sizes, int n_in,
                              void* d_out, int out_size)
{
    const float* query  = (const float*)d_in[0];
    const float* keys   = (const float*)d_in[1];
    const float* rot    = (const float*)d_in[2];
    const float* S      = (const float*)d_in[3];
    const float* levels = (const float*)d_in[4];
    float* out = (float*)d_out;

    prep_all<<<Dn, Dn>>>(query, rot, S);
    turbo_main<<<NBLOCKS, NTHREADS>>>(keys, rot, levels, out);
}

// round 7
// speedup vs baseline: 2.1125x; 1.0372x over previous
#include <cuda_runtime.h>
#include <math.h>

#define Dn   128
#define SQn  16
#define SKn  4096
#define BHn  64
#define TILE 64
#define NTHREADS 256
#define NWARPS   8
#define NBLOCKS  (BHn * (SKn / TILE))   /* 4096 */

/* device scratch (no allocation allowed) */
__device__ float g_Rt[Dn*Dn];     /* Rt[d][j] = R[j][d] */
__device__ float g_St[Dn*Dn];     /* St[d][m] = S[m][d] */
__device__ float g_qR[BHn*SQn*Dn];
__device__ float g_qS[BHn*SQn*Dn];

/* ---- merged prep: transposes + qR/qS ---- */
__global__ void prep_all(const float* __restrict__ query,
                         const float* __restrict__ rot,
                         const float* __restrict__ S)
{
    int j = blockIdx.x, t = threadIdx.x;       /* 128 x 128 */
    g_Rt[t*Dn + j] = rot[j*Dn + t];
    g_St[t*Dn + j] = S[j*Dn + t];

    if (blockIdx.x < BHn) {
        int bh = blockIdx.x;
        const float* qbase = query + (size_t)bh*SQn*Dn;
#pragma unroll
        for (int c = 0; c < (SQn*Dn)/128; ++c) {
            int o = t + c*128;
            int q = o >> 7, jj = o & 127;
            const float* qp = qbase + q*Dn;
            const float* rp = rot + jj*Dn;
            const float* sp = S   + jj*Dn;
            float aR = 0.f, aS = 0.f;
#pragma unroll 8
            for (int d = 0; d < Dn; ++d) {
                float qq = __ldg(qp + d);
                aR = __fmaf_rn(qq, __ldg(rp + d), aR);
                aS = __fmaf_rn(qq, __ldg(sp + d), aS);
            }
            g_qR[bh*SQn*Dn + o] = aR;
            g_qS[bh*SQn*Dn + o] = aS;
        }
    }
}

__device__ __forceinline__ float wsum(float v)
{
#pragma unroll
    for (int o = 16; o > 0; o >>= 1) v += __shfl_xor_sync(0xffffffffu, v, o);
    return v;
}

/* 8-key matvec pass: one matrix float4 load feeds 32 FFMA.
 * Per-key FMA chain order over d is unchanged (decision-bit-identical). */
#define MV8_ROWS(PP, MAT)                                           \
    _Pragma("unroll 2")                                             \
    for (int db = 0; db < Dn; db += 4) {                            \
        float xs[8][4];                                             \
        _Pragma("unroll")                                           \
        for (int i = 0; i < 8; ++i) {                               \
            float4 x = *(const float4*)((PP)[i] + db);              \
            xs[i][0]=x.x; xs[i][1]=x.y; xs[i][2]=x.z; xs[i][3]=x.w; \
        }                                                           \
        _Pragma("unroll")                                           \
        for (int dd = 0; dd < 4; ++dd) {                            \
            float4 r = ((const float4*)(MAT))[(db+dd)*32 + lane];   \
            _Pragma("unroll")                                       \
            for (int i = 0; i < 8; ++i) {                           \
                float x = xs[i][dd];                                \
                a[i].x = __fmaf_rn(x, r.x, a[i].x);                 \
                a[i].y = __fmaf_rn(x, r.y, a[i].y);                 \
                a[i].z = __fmaf_rn(x, r.z, a[i].z);                 \
                a[i].w = __fmaf_rn(x, r.w, a[i].w);                 \
            }                                                       \
        }                                                           \
    }

/* ---- main fused kernel: one block = 64 keys of one (b,h), 8 warps ---- */
__global__ void __launch_bounds__(NTHREADS, 1)
turbo_main(const float* __restrict__ keys, const float* __restrict__ rot,
           const float* __restrict__ levels, float* __restrict__ out)
{
    __shared__ float  sM[Dn*Dn];        /* 64K: Rt -> rot -> St  */
    __shared__ float  sK[TILE*Dn];      /* 32K: keys -> k_hat -> r_hat */
    __shared__ float  sQR[SQn*Dn];      /*  8K */
    __shared__ float  sQS[SQn*Dn];      /*  8K */
    __shared__ float  sTab[256*4];      /*  4K: byte -> 4 level values */
    __shared__ float  sNorm[TILE];
    __shared__ float  sRn[TILE];
    __shared__ unsigned sSign[TILE*4];  /*  1K */
    __shared__ unsigned char sCodeB[TILE*32]; /* 2K: 2-bit yhat codes */

    const int tid = threadIdx.x, w = tid >> 5, lane = tid & 31;
    const int bh  = blockIdx.x >> 6;            /* 64 tiles per bh */
    const int k0  = (blockIdx.x & 63) * TILE;
    const float* keys_blk = keys + ((size_t)bh*SKn + k0)*Dn;

    const float L0 = __ldg(levels+0), L1 = __ldg(levels+1),
                L2 = __ldg(levels+2), L3 = __ldg(levels+3);
    const float bb0 = 0.5f*(L0+L1), bb1 = 0.5f*(L1+L2), bb2 = 0.5f*(L2+L3);

    /* cooperative loads */
    {
        const float4* g = (const float4*)keys_blk;
        float4* s = (float4*)sK;
#pragma unroll
        for (int i = tid; i < TILE*Dn/4; i += NTHREADS) s[i] = g[i];
    }
    {
        const float4* g = (const float4*)g_Rt; float4* s = (float4*)sM;
#pragma unroll
        for (int i = tid; i < Dn*Dn/4; i += NTHREADS) s[i] = g[i];
    }
    {
        const float4* g = (const float4*)(g_qR + bh*SQn*Dn); float4* s = (float4*)sQR;
#pragma unroll
        for (int i = tid; i < SQn*Dn/4; i += NTHREADS) s[i] = g[i];
        g = (const float4*)(g_qS + bh*SQn*Dn); s = (float4*)sQS;
#pragma unroll
        for (int i = tid; i < SQn*Dn/4; i += NTHREADS) s[i] = g[i];
    }
    /* byte -> float4 level decode table (exact level values) */
    {
        unsigned b = tid;
        float v[4];
#pragma unroll
        for (int c = 0; c < 4; ++c) {
            unsigned cc = (b >> (2*c)) & 3u;
            float lo = (cc & 1u) ? L1 : L0;
            float hi = (cc & 1u) ? L3 : L2;
            v[c] = (cc & 2u) ? hi : lo;
        }
        ((float4*)sTab)[b] = make_float4(v[0],v[1],v[2],v[3]);
    }
    __syncthreads();

    /* norms (fp32, deterministic order); each warp owns 8 keys */
#pragma unroll
    for (int i = 0; i < 8; ++i) {
        int key = w*8 + i;
        float4 v = ((const float4*)(sK + key*Dn))[lane];
        float ss = __fmul_rn(v.x, v.x);
        ss = __fmaf_rn(v.y, v.y, ss);
        ss = __fmaf_rn(v.z, v.z, ss);
        ss = __fmaf_rn(v.w, v.w, ss);
        ss = wsum(ss);
        if (lane == 0) sNorm[key] = fmaxf(__fsqrt_rn(ss), 1e-8f);
    }
    __syncthreads();

    /* k_hat = fl(k / n) in place (IEEE div) */
#pragma unroll
    for (int i = tid; i < TILE*Dn; i += NTHREADS)
        sK[i] = __fdiv_rn(sK[i], sNorm[i >> 7]);
    __syncthreads();

    const int kb = w*8;

    /* ===== phase 1: y = k_hat @ R^T (seq FMA over d); 2-bit codes ===== */
    {
        const float* pp[8];
#pragma unroll
        for (int i = 0; i < 8; ++i) pp[i] = sK + (kb+i)*Dn;
        float4 a[8];
#pragma unroll
        for (int i = 0; i < 8; ++i) a[i] = make_float4(0.f,0.f,0.f,0.f);
        MV8_ROWS(pp, sM)
#pragma unroll
        for (int i = 0; i < 8; ++i) {
            unsigned c0, c1, c2, c3;
            { float y = a[i].x; c0 = (unsigned)(y > bb0) + (unsigned)(y > bb1) + (unsigned)(y > bb2); }
            { float y = a[i].y; c1 = (unsigned)(y > bb0) + (unsigned)(y > bb1) + (unsigned)(y > bb2); }
            { float y = a[i].z; c2 = (unsigned)(y > bb0) + (unsigned)(y > bb1) + (unsigned)(y > bb2); }
            { float y = a[i].w; c3 = (unsigned)(y > bb0) + (unsigned)(y > bb1) + (unsigned)(y > bb2); }
            sCodeB[(kb+i)*32 + lane] = (unsigned char)(c0 | (c1<<2) | (c2<<4) | (c3<<6));
        }
    }
    __syncthreads();

    /* reload matrix slot with R itself (row-major rot[j][d]) */
    {
        const float4* g = (const float4*)rot; float4* s = (float4*)sM;
#pragma unroll
        for (int i = tid; i < Dn*Dn/4; i += NTHREADS) s[i] = g[i];
    }
    __syncthreads();

    /* ===== phase 2: keys_mse = fl(fl(yhat@R)*n); residual; r_hat ===== */
    {
        const unsigned char* cp[8];
#pragma unroll
        for (int i = 0; i < 8; ++i) cp[i] = sCodeB + (kb+i)*32;
        float4 a[8];
#pragma unroll
        for (int i = 0; i < 8; ++i) a[i] = make_float4(0.f,0.f,0.f,0.f);
#pragma unroll 2
        for (int g = 0; g < 32; ++g) {          /* j = 4g..4g+3 */
            float xs[8][4];
#pragma unroll
            for (int i = 0; i < 8; ++i) {
                float4 x = ((const float4*)sTab)[cp[i][g]];
                xs[i][0]=x.x; xs[i][1]=x.y; xs[i][2]=x.z; xs[i][3]=x.w;
            }
#pragma unroll
            for (int dd = 0; dd < 4; ++dd) {
                float4 r = ((const float4*)sM)[(4*g+dd)*32 + lane];
#pragma unroll
                for (int i = 0; i < 8; ++i) {
                    float x = xs[i][dd];
                    a[i].x = __fmaf_rn(x, r.x, a[i].x);
                    a[i].y = __fmaf_rn(x, r.y, a[i].y);
                    a[i].z = __fmaf_rn(x, r.z, a[i].z);
                    a[i].w = __fmaf_rn(x, r.w, a[i].w);
                }
            }
        }
#pragma unroll
        for (int i = 0; i < 8; ++i) {
            int key = kb + i;
            float n = sNorm[key];
            float4 kg = ((const float4*)(keys_blk + (size_t)key*Dn))[lane];
            float4 r;
            r.x = __fadd_rn(kg.x, -__fmul_rn(a[i].x, n));
            r.y = __fadd_rn(kg.y, -__fmul_rn(a[i].y, n));
            r.z = __fadd_rn(kg.z, -__fmul_rn(a[i].z, n));
            r.w = __fadd_rn(kg.w, -__fmul_rn(a[i].w, n));
            float ss = __fmul_rn(r.x, r.x);
            ss = __fmaf_rn(r.y, r.y, ss);
            ss = __fmaf_rn(r.z, r.z, ss);
            ss = __fmaf_rn(r.w, r.w, ss);
            ss = wsum(ss);
            float rn = fmaxf(__fsqrt_rn(ss), 1e-10f);
            if (lane == 0) sRn[key] = rn;
            float4 rh;
            rh.x = __fdiv_rn(r.x, rn);
            rh.y = __fdiv_rn(r.y, rn);
            rh.z = __fdiv_rn(r.z, rn);
            rh.w = __fdiv_rn(r.w, rn);
            ((float4*)(sK + key*Dn))[lane] = rh;   /* k_hat -> r_hat */
        }
    }
    __syncthreads();

    /* reload matrix slot: St[d][m] */
    {
        const float4* g = (const float4*)g_St; float4* s = (float4*)sM;
#pragma unroll
        for (int i = tid; i < Dn*Dn/4; i += NTHREADS) s[i] = g[i];
    }
    __syncthreads();

    /* ===== phase 3: proj = r_hat @ S^T (seq FMA over d); signs ===== */
    {
        const float* pp[8];
#pragma unroll
        for (int i = 0; i < 8; ++i) pp[i] = sK + (kb+i)*Dn;
        float4 a[8];
#pragma unroll
        for (int i = 0; i < 8; ++i) a[i] = make_float4(0.f,0.f,0.f,0.f);
        MV8_ROWS(pp, sM)
#pragma unroll
        for (int i = 0; i < 8; ++i) {
            unsigned b0 = __ballot_sync(0xffffffffu, a[i].x >= 0.f);
            unsigned b1 = __ballot_sync(0xffffffffu, a[i].y >= 0.f);
            unsigned b2 = __ballot_sync(0xffffffffu, a[i].z >= 0.f);
            unsigned b3 = __ballot_sync(0xffffffffu, a[i].w >= 0.f);
            if (lane == 0) {
                unsigned* sp = sSign + (size_t)(kb+i)*4;
                sp[0]=b0; sp[1]=b1; sp[2]=b2; sp[3]=b3;
            }
        }
    }
    __syncthreads();

    /* ===== epilogue (shfl-free): warp -> 2 q rows, lane -> keys {lane, lane+32} ===== */
    {
        const float cq = 0.0097915167f;   /* sqrt(pi/2)/128 */
        const int q0 = 2*w, q1 = 2*w + 1;
        const int kA = lane, kB = lane + 32;
        const float* qr0 = sQR + q0*Dn;
        const float* qr1 = sQR + q1*Dn;
        const float* qs0 = sQS + q0*Dn;
        const float* qs1 = sQS + q1*Dn;
        const unsigned char* cA = sCodeB + kA*32;
        const unsigned char* cB = sCodeB + kB*32;

        float e00 = 0.f, e01 = 0.f, e10 = 0.f, e11 = 0.f;
#pragma unroll 4
        for (int g = 0; g < 32; ++g) {
            float4 a0 = ((const float4*)qr0)[g];
            float4 a1 = ((const float4*)qr1)[g];
            float4 yA = ((const float4*)sTab)[cA[g]];
            float4 yB = ((const float4*)sTab)[cB[g]];
            e00 = __fmaf_rn(a0.x, yA.x, e00); e00 = __fmaf_rn(a0.y, yA.y, e00);
            e00 = __fmaf_rn(a0.z, yA.z, e00); e00 = __fmaf_rn(a0.w, yA.w, e00);
            e01 = __fmaf_rn(a0.x, yB.x, e01); e01 = __fmaf_rn(a0.y, yB.y, e01);
            e01 = __fmaf_rn(a0.z, yB.z, e01); e01 = __fmaf_rn(a0.w, yB.w, e01);
            e10 = __fmaf_rn(a1.x, yA.x, e10); e10 = __fmaf_rn(a1.y, yA.y, e10);
            e10 = __fmaf_rn(a1.z, yA.z, e10); e10 = __fmaf_rn(a1.w, yA.w, e10);
            e11 = __fmaf_rn(a1.x, yB.x, e11); e11 = __fmaf_rn(a1.y, yB.y, e11);
            e11 = __fmaf_rn(a1.z, yB.z, e11); e11 = __fmaf_rn(a1.w, yB.w, e11);
        }

        unsigned wA0 = sSign[kA*4+0], wA1 = sSign[kA*4+1],
                 wA2 = sSign[kA*4+2], wA3 = sSign[kA*4+3];
        unsigned wB0 = sSign[kB*4+0], wB1 = sSign[kB*4+1],
                 wB2 = sSign[kB*4+2], wB3 = sSign[kB*4+3];

        float s00 = 0.f, s01 = 0.f, s10 = 0.f, s11 = 0.f;
#pragma unroll 4
        for (int g = 0; g < 32; ++g) {        /* m = 4g + c, bit g of word c */
            float4 b0 = ((const float4*)qs0)[g];
            float4 b1 = ((const float4*)qs1)[g];
            float fA0 = ((wA0 >> g) & 1u) ? 1.f : -1.f;
            float fA1 = ((wA1 >> g) & 1u) ? 1.f : -1.f;
            float fA2 = ((wA2 >> g) & 1u) ? 1.f : -1.f;
            float fA3 = ((wA3 >> g) & 1u) ? 1.f : -1.f;
            float fB0 = ((wB0 >> g) & 1u) ? 1.f : -1.f;
            float fB1 = ((wB1 >> g) & 1u) ? 1.f : -1.f;
            float fB2 = ((wB2 >> g) & 1u) ? 1.f : -1.f;
            float fB3 = ((wB3 >> g) & 1u) ? 1.f : -1.f;
            s00 = __fmaf_rn(fA0, b0.x, s00); s00 = __fmaf_rn(fA1, b0.y, s00);
            s00 = __fmaf_rn(fA2, b0.z, s00); s00 = __fmaf_rn(fA3, b0.w, s00);
            s01 = __fmaf_rn(fB0, b0.x, s01); s01 = __fmaf_rn(fB1, b0.y, s01);
            s01 = __fmaf_rn(fB2, b0.z, s01); s01 = __fmaf_rn(fB3, b0.w, s01);
            s10 = __fmaf_rn(fA0, b1.x, s10); s10 = __fmaf_rn(fA1, b1.y, s10);
            s10 = __fmaf_rn(fA2, b1.z, s10); s10 = __fmaf_rn(fA3, b1.w, s10);
            s11 = __fmaf_rn(fB0, b1.x, s11); s11 = __fmaf_rn(fB1, b1.y, s11);
            s11 = __fmaf_rn(fB2, b1.z, s11); s11 = __fmaf_rn(fB3, b1.w, s11);
        }

        float nA = sNorm[kA], nB = sNorm[kB];
        float gA = cq * sRn[kA], gB = cq * sRn[kB];
        float* og = out + ((size_t)bh*SQn)*SKn + k0;
        og[(size_t)q0*SKn + kA] = nA*e00 + gA*s00;
        og[(size_t)q0*SKn + kB] = nB*e01 + gB*s01;
        og[(size_t)q1*SKn + kA] = nA*e10 + gA*s10;
        og[(size_t)q1*SKn + kB] = nB*e11 + gB*s11;
    }
}

extern "C" void kernel_launch(void* const* d_in, const int* in_sizes, int n_in,
                              void* d_out, int out_size)
{
    const float* query  = (const float*)d_in[0];
    const float* keys   = (const float*)d_in[1];
    const float* rot    = (const float*)d_in[2];
    const float* S      = (const float*)d_in[3];
    const float* levels = (const float*)d_in[4];
    float* out = (float*)d_out;

    prep_all<<<Dn, Dn>>>(query, rot, S);
    turbo_main<<<NBLOCKS, NTHREADS>>>(keys, rot, levels, out);
}

// round 8
// speedup vs baseline: 2.1230x; 1.0050x over previous
#include <cuda_runtime.h>
#include <math.h>

#define Dn   128
#define SQn  16
#define SKn  4096
#define BHn  64
#define TILE 64
#define NTHREADS 256
#define NWARPS   8
#define NBLOCKS  (BHn * (SKn / TILE))   /* 4096 */

typedef unsigned long long u64;

/* device scratch (no allocation allowed) */
__device__ float g_Rt[Dn*Dn];     /* Rt[d][j] = R[j][d] */
__device__ float g_St[Dn*Dn];     /* St[d][m] = S[m][d] */
__device__ float g_qR[BHn*SQn*Dn];
__device__ float g_qS[BHn*SQn*Dn];

/* ---- merged prep: transposes + qR/qS ---- */
__global__ void prep_all(const float* __restrict__ query,
                         const float* __restrict__ rot,
                         const float* __restrict__ S)
{
    int j = blockIdx.x, t = threadIdx.x;       /* 128 x 128 */
    g_Rt[t*Dn + j] = rot[j*Dn + t];
    g_St[t*Dn + j] = S[j*Dn + t];

    if (blockIdx.x < BHn) {
        int bh = blockIdx.x;
        const float* qbase = query + (size_t)bh*SQn*Dn;
#pragma unroll
        for (int c = 0; c < (SQn*Dn)/128; ++c) {
            int o = t + c*128;
            int q = o >> 7, jj = o & 127;
            const float* qp = qbase + q*Dn;
            const float* rp = rot + jj*Dn;
            const float* sp = S   + jj*Dn;
            float aR = 0.f, aS = 0.f;
#pragma unroll 8
            for (int d = 0; d < Dn; ++d) {
                float qq = __ldg(qp + d);
                aR = __fmaf_rn(qq, __ldg(rp + d), aR);
                aS = __fmaf_rn(qq, __ldg(sp + d), aS);
            }
            g_qR[bh*SQn*Dn + o] = aR;
            g_qS[bh*SQn*Dn + o] = aS;
        }
    }
}

__device__ __forceinline__ float wsum(float v)
{
#pragma unroll
    for (int o = 16; o > 0; o >>= 1) v += __shfl_xor_sync(0xffffffffu, v, o);
    return v;
}

/* ---- packed f32x2 helpers (each = two independent IEEE fp32 ops) ---- */
__device__ __forceinline__ u64 pk2(float lo, float hi)
{ u64 r; asm("mov.b64 %0,{%1,%2};" : "=l"(r) : "f"(lo), "f"(hi)); return r; }
__device__ __forceinline__ u64 dup2(float x)
{ u64 r; asm("mov.b64 %0,{%1,%1};" : "=l"(r) : "f"(x)); return r; }
__device__ __forceinline__ void fma2(u64& acc, u64 a, u64 b)
{ asm("fma.rn.f32x2 %0,%1,%2,%0;" : "+l"(acc) : "l"(a), "l"(b)); }
__device__ __forceinline__ void add2(u64& acc, u64 v)
{ asm("add.rn.f32x2 %0,%1,%0;" : "+l"(acc) : "l"(v)); }
__device__ __forceinline__ float2 unpk(u64 v)
{ float2 f; asm("mov.b64 {%0,%1},%2;" : "=f"(f.x), "=f"(f.y) : "l"(v)); return f; }

/* 8-key packed matvec pass: per-component FMA chain order over d unchanged
 * vs scalar FFMA version -> decision-bit-identical. */
#define MV8_F32X2(PP, MAT)                                          \
    _Pragma("unroll 2")                                             \
    for (int db = 0; db < Dn; db += 4) {                            \
        float xs[8][4];                                             \
        _Pragma("unroll")                                           \
        for (int i = 0; i < 8; ++i) {                               \
            float4 x = *(const float4*)((PP)[i] + db);              \
            xs[i][0]=x.x; xs[i][1]=x.y; xs[i][2]=x.z; xs[i][3]=x.w; \
        }                                                           \
        _Pragma("unroll")                                           \
        for (int dd = 0; dd < 4; ++dd) {                            \
            float4 r = ((const float4*)(MAT))[(db+dd)*32 + lane];   \
            u64 rxy = pk2(r.x, r.y);                                \
            u64 rzw = pk2(r.z, r.w);                                \
            _Pragma("unroll")                                       \
            for (int i = 0; i < 8; ++i) {                           \
                u64 xx = dup2(xs[i][dd]);                           \
                fma2(axy[i], xx, rxy);                              \
                fma2(azw[i], xx, rzw);                              \
            }                                                       \
        }                                                           \
    }

/* ---- main fused kernel: one block = 64 keys of one (b,h), 8 warps ---- */
__global__ void __launch_bounds__(NTHREADS, 1)
turbo_main(const float* __restrict__ keys, const float* __restrict__ rot,
           const float* __restrict__ levels, float* __restrict__ out)
{
    __shared__ float  sM[Dn*Dn];        /* 64K: Rt -> rot -> St  */
    __shared__ float  sK[TILE*Dn];      /* 32K: keys -> k_hat -> r_hat */
    __shared__ float  sQR[SQn*Dn];      /*  8K */
    __shared__ float  sQS[SQn*Dn];      /*  8K */
    __shared__ float  sTab[256*4];      /*  4K: byte -> 4 level values */
    __shared__ float  sNorm[TILE];
    __shared__ float  sRn[TILE];
    __shared__ unsigned sSign[TILE*4];  /*  1K */
    __shared__ unsigned char sCodeB[TILE*32]; /* 2K: 2-bit yhat codes */

    const int tid = threadIdx.x, w = tid >> 5, lane = tid & 31;
    const int bh  = blockIdx.x >> 6;            /* 64 tiles per bh */
    const int k0  = (blockIdx.x & 63) * TILE;
    const float* keys_blk = keys + ((size_t)bh*SKn + k0)*Dn;

    const float L0 = __ldg(levels+0), L1 = __ldg(levels+1),
                L2 = __ldg(levels+2), L3 = __ldg(levels+3);
    const float bb0 = 0.5f*(L0+L1), bb1 = 0.5f*(L1+L2), bb2 = 0.5f*(L2+L3);

    /* cooperative loads */
    {
        const float4* g = (const float4*)keys_blk;
        float4* s = (float4*)sK;
#pragma unroll
        for (int i = tid; i < TILE*Dn/4; i += NTHREADS) s[i] = g[i];
    }
    {
        const float4* g = (const float4*)g_Rt; float4* s = (float4*)sM;
#pragma unroll
        for (int i = tid; i < Dn*Dn/4; i += NTHREADS) s[i] = g[i];
    }
    {
        const float4* g = (const float4*)(g_qR + bh*SQn*Dn); float4* s = (float4*)sQR;
#pragma unroll
        for (int i = tid; i < SQn*Dn/4; i += NTHREADS) s[i] = g[i];
        g = (const float4*)(g_qS + bh*SQn*Dn); s = (float4*)sQS;
#pragma unroll
        for (int i = tid; i < SQn*Dn/4; i += NTHREADS) s[i] = g[i];
    }
    /* byte -> float4 level decode table (exact level values) */
    {
        unsigned b = tid;
        float v[4];
#pragma unroll
        for (int c = 0; c < 4; ++c) {
            unsigned cc = (b >> (2*c)) & 3u;
            float lo = (cc & 1u) ? L1 : L0;
            float hi = (cc & 1u) ? L3 : L2;
            v[c] = (cc & 2u) ? hi : lo;
        }
        ((float4*)sTab)[b] = make_float4(v[0],v[1],v[2],v[3]);
    }
    __syncthreads();

    /* norms (fp32, deterministic order); each warp owns 8 keys */
#pragma unroll
    for (int i = 0; i < 8; ++i) {
        int key = w*8 + i;
        float4 v = ((const float4*)(sK + key*Dn))[lane];
        float ss = __fmul_rn(v.x, v.x);
        ss = __fmaf_rn(v.y, v.y, ss);
        ss = __fmaf_rn(v.z, v.z, ss);
        ss = __fmaf_rn(v.w, v.w, ss);
        ss = wsum(ss);
        if (lane == 0) sNorm[key] = fmaxf(__fsqrt_rn(ss), 1e-8f);
    }
    __syncthreads();

    /* k_hat = fl(k / n) in place (IEEE div) */
#pragma unroll
    for (int i = tid; i < TILE*Dn; i += NTHREADS)
        sK[i] = __fdiv_rn(sK[i], sNorm[i >> 7]);
    __syncthreads();

    const int kb = w*8;

    /* ===== phase 1: y = k_hat @ R^T (seq FMA over d); 2-bit codes ===== */
    {
        const float* pp[8];
#pragma unroll
        for (int i = 0; i < 8; ++i) pp[i] = sK + (kb+i)*Dn;
        u64 axy[8], azw[8];
#pragma unroll
        for (int i = 0; i < 8; ++i) { axy[i] = 0ULL; azw[i] = 0ULL; }
        MV8_F32X2(pp, sM)
#pragma unroll
        for (int i = 0; i < 8; ++i) {
            float2 lo = unpk(axy[i]), hi = unpk(azw[i]);
            unsigned c0, c1, c2, c3;
            { float y = lo.x; c0 = (unsigned)(y > bb0) + (unsigned)(y > bb1) + (unsigned)(y > bb2); }
            { float y = lo.y; c1 = (unsigned)(y > bb0) + (unsigned)(y > bb1) + (unsigned)(y > bb2); }
            { float y = hi.x; c2 = (unsigned)(y > bb0) + (unsigned)(y > bb1) + (unsigned)(y > bb2); }
            { float y = hi.y; c3 = (unsigned)(y > bb0) + (unsigned)(y > bb1) + (unsigned)(y > bb2); }
            sCodeB[(kb+i)*32 + lane] = (unsigned char)(c0 | (c1<<2) | (c2<<4) | (c3<<6));
        }
    }
    __syncthreads();

    /* reload matrix slot with R itself (row-major rot[j][d]) */
    {
        const float4* g = (const float4*)rot; float4* s = (float4*)sM;
#pragma unroll
        for (int i = tid; i < Dn*Dn/4; i += NTHREADS) s[i] = g[i];
    }
    __syncthreads();

    /* ===== phase 2: keys_mse = fl(fl(yhat@R)*n); residual; r_hat ===== */
    {
        const unsigned char* cp[8];
#pragma unroll
        for (int i = 0; i < 8; ++i) cp[i] = sCodeB + (kb+i)*32;
        u64 axy[8], azw[8];
#pragma unroll
        for (int i = 0; i < 8; ++i) { axy[i] = 0ULL; azw[i] = 0ULL; }
#pragma unroll 2
        for (int g = 0; g < 32; ++g) {          /* j = 4g..4g+3 */
            float xs[8][4];
#pragma unroll
            for (int i = 0; i < 8; ++i) {
                float4 x = ((const float4*)sTab)[cp[i][g]];
                xs[i][0]=x.x; xs[i][1]=x.y; xs[i][2]=x.z; xs[i][3]=x.w;
            }
#pragma unroll
            for (int dd = 0; dd < 4; ++dd) {
                float4 r = ((const float4*)sM)[(4*g+dd)*32 + lane];
                u64 rxy = pk2(r.x, r.y);
                u64 rzw = pk2(r.z, r.w);
#pragma unroll
                for (int i = 0; i < 8; ++i) {
                    u64 xx = dup2(xs[i][dd]);
                    fma2(axy[i], xx, rxy);
                    fma2(azw[i], xx, rzw);
                }
            }
        }
#pragma unroll
        for (int i = 0; i < 8; ++i) {
            int key = kb + i;
            float n = sNorm[key];
            float2 lo = unpk(axy[i]), hi = unpk(azw[i]);
            float4 kg = ((const float4*)(keys_blk + (size_t)key*Dn))[lane];
            float4 r;
            r.x = __fadd_rn(kg.x, -__fmul_rn(lo.x, n));
            r.y = __fadd_rn(kg.y, -__fmul_rn(lo.y, n));
            r.z = __fadd_rn(kg.z, -__fmul_rn(hi.x, n));
            r.w = __fadd_rn(kg.w, -__fmul_rn(hi.y, n));
            float ss = __fmul_rn(r.x, r.x);
            ss = __fmaf_rn(r.y, r.y, ss);
            ss = __fmaf_rn(r.z, r.z, ss);
            ss = __fmaf_rn(r.w, r.w, ss);
            ss = wsum(ss);
            float rn = fmaxf(__fsqrt_rn(ss), 1e-10f);
            if (lane == 0) sRn[key] = rn;
            float4 rh;
            rh.x = __fdiv_rn(r.x, rn);
            rh.y = __fdiv_rn(r.y, rn);
            rh.z = __fdiv_rn(r.z, rn);
            rh.w = __fdiv_rn(r.w, rn);
            ((float4*)(sK + key*Dn))[lane] = rh;   /* k_hat -> r_hat */
        }
    }
    __syncthreads();

    /* reload matrix slot: St[d][m] */
    {
        const float4* g = (const float4*)g_St; float4* s = (float4*)sM;
#pragma unroll
        for (int i = tid; i < Dn*Dn/4; i += NTHREADS) s[i] = g[i];
    }
    __syncthreads();

    /* ===== phase 3: proj = r_hat @ S^T (seq FMA over d); signs ===== */
    {
        const float* pp[8];
#pragma unroll
        for (int i = 0; i < 8; ++i) pp[i] = sK + (kb+i)*Dn;
        u64 axy[8], azw[8];
#pragma unroll
        for (int i = 0; i < 8; ++i) { axy[i] = 0ULL; azw[i] = 0ULL; }
        MV8_F32X2(pp, sM)
#pragma unroll
        for (int i = 0; i < 8; ++i) {
            float2 lo = unpk(axy[i]), hi = unpk(azw[i]);
            unsigned b0 = __ballot_sync(0xffffffffu, lo.x >= 0.f);
            unsigned b1 = __ballot_sync(0xffffffffu, lo.y >= 0.f);
            unsigned b2 = __ballot_sync(0xffffffffu, hi.x >= 0.f);
            unsigned b3 = __ballot_sync(0xffffffffu, hi.y >= 0.f);
            if (lane == 0) {
                unsigned* sp = sSign + (size_t)(kb+i)*4;
                sp[0]=b0; sp[1]=b1; sp[2]=b2; sp[3]=b3;
            }
        }
    }
    __syncthreads();

    /* ===== epilogue (shfl-free, packed): warp -> 2 q rows, lane -> keys {lane, lane+32} ===== */
    {
        const float cq = 0.0097915167f;   /* sqrt(pi/2)/128 */
        const int q0 = 2*w, q1 = 2*w + 1;
        const int kA = lane, kB = lane + 32;
        const float* qr0 = sQR + q0*Dn;
        const float* qr1 = sQR + q1*Dn;
        const float* qs0 = sQS + q0*Dn;
        const float* qs1 = sQS + q1*Dn;
        const unsigned char* cA = sCodeB + kA*32;
        const unsigned char* cB = sCodeB + kB*32;

        u64 E00 = 0, E01 = 0, E10 = 0, E11 = 0;
#pragma unroll 4
        for (int g = 0; g < 32; ++g) {
            float4 a0 = ((const float4*)qr0)[g];
            float4 a1 = ((const float4*)qr1)[g];
            float4 yA = ((const float4*)sTab)[cA[g]];
            float4 yB = ((const float4*)sTab)[cB[g]];
            u64 a0xy = pk2(a0.x,a0.y), a0zw = pk2(a0.z,a0.w);
            u64 a1xy = pk2(a1.x,a1.y), a1zw = pk2(a1.z,a1.w);
            u64 yAxy = pk2(yA.x,yA.y), yAzw = pk2(yA.z,yA.w);
            u64 yBxy = pk2(yB.x,yB.y), yBzw = pk2(yB.z,yB.w);
            fma2(E00, a0xy, yAxy); fma2(E00, a0zw, yAzw);
            fma2(E01, a0xy, yBxy); fma2(E01, a0zw, yBzw);
            fma2(E10, a1xy, yAxy); fma2(E10, a1zw, yAzw);
            fma2(E11, a1xy, yBxy); fma2(E11, a1zw, yBzw);
        }

        unsigned wA0 = sSign[kA*4+0], wA1 = sSign[kA*4+1],
                 wA2 = sSign[kA*4+2], wA3 = sSign[kA*4+3];
        unsigned wB0 = sSign[kB*4+0], wB1 = sSign[kB*4+1],
                 wB2 = sSign[kB*4+2], wB3 = sSign[kB*4+3];

        u64 S00 = 0, S01 = 0, S10 = 0, S11 = 0;
#pragma unroll 4
        for (int g = 0; g < 32; ++g) {        /* m = 4g + c, bit g of word c */
            float4 b0 = ((const float4*)qs0)[g];
            float4 b1 = ((const float4*)qs1)[g];
            u64 b0xy = pk2(b0.x,b0.y), b0zw = pk2(b0.z,b0.w);
            u64 b1xy = pk2(b1.x,b1.y), b1zw = pk2(b1.z,b1.w);
            /* negate (sign-bit XOR, exact) where ballot bit is 0 */
            u64 mAxy = ((u64)(((wA0 >> g) & 1u) ^ 1u) << 31) | ((u64)(((wA1 >> g) & 1u) ^ 1u) << 63);
            u64 mAzw = ((u64)(((wA2 >> g) & 1u) ^ 1u) << 31) | ((u64)(((wA3 >> g) & 1u) ^ 1u) << 63);
            u64 mBxy = ((u64)(((wB0 >> g) & 1u) ^ 1u) << 31) | ((u64)(((wB1 >> g) & 1u) ^ 1u) << 63);
            u64 mBzw = ((u64)(((wB2 >> g) & 1u) ^ 1u) << 31) | ((u64)(((wB3 >> g) & 1u) ^ 1u) << 63);
            add2(S00, b0xy ^ mAxy); add2(S00, b0zw ^ mAzw);
            add2(S01, b0xy ^ mBxy); add2(S01, b0zw ^ mBzw);
            add2(S10, b1xy ^ mAxy); add2(S10, b1zw ^ mAzw);
            add2(S11, b1xy ^ mBxy); add2(S11, b1zw ^ mBzw);
        }

        float2 f;
        f = unpk(E00); float e00 = f.x + f.y;
        f = unpk(E01); float e01 = f.x + f.y;
        f = unpk(E10); float e10 = f.x + f.y;
        f = unpk(E11); float e11 = f.x + f.y;
        f = unpk(S00); float s00 = f.x + f.y;
        f = unpk(S01); float s01 = f.x + f.y;
        f = unpk(S10); float s10 = f.x + f.y;
        f = unpk(S11); float s11 = f.x + f.y;

        float nA = sNorm[kA], nB = sNorm[kB];
        float gA = cq * sRn[kA], gB = cq * sRn[kB];
        float* og = out + ((size_t)bh*SQn)*SKn + k0;
        og[(size_t)q0*SKn + kA] = nA*e00 + gA*s00;
        og[(size_t)q0*SKn + kB] = nB*e01 + gB*s01;
        og[(size_t)q1*SKn + kA] = nA*e10 + gA*s10;
        og[(size_t)q1*SKn + kB] = nB*e11 + gB*s11;
    }
}

extern "C" void kernel_launch(void* const* d_in, const int* in_sizes, int n_in,
                              void* d_out, int out_size)
{
    const float* query  = (const float*)d_in[0];
    const float* keys   = (const float*)d_in[1];
    const float* rot    = (const float*)d_in[2];
    const float* S      = (const float*)d_in[3];
    const float* levels = (const float*)d_in[4];
    float* out = (float*)d_out;

    prep_all<<<Dn, Dn>>>(query, rot, S);
    turbo_main<<<NBLOCKS, NTHREADS>>>(keys, rot, levels, out);
}

// round 9
// speedup vs baseline: 2.1424x; 1.0092x over previous
#include <cuda_runtime.h>
#include <math.h>

#define Dn   128
#define SQn  16
#define SKn  4096
#define BHn  64
#define TILE 128
#define NTHREADS 256
#define NWARPS   8
#define NBLOCKS  (BHn * (SKn / TILE))   /* 2048 */

typedef unsigned long long u64;

/* device scratch (no allocation allowed) */
__device__ float g_Rt[Dn*Dn];     /* Rt[d][j] = R[j][d] */
__device__ float g_St[Dn*Dn];     /* St[d][m] = S[m][d] */
__device__ float g_qR[BHn*SQn*Dn];
__device__ float g_qS[BHn*SQn*Dn];

/* ---- merged prep: transposes + qR/qS ---- */
__global__ void prep_all(const float* __restrict__ query,
                         const float* __restrict__ rot,
                         const float* __restrict__ S)
{
    int j = blockIdx.x, t = threadIdx.x;       /* 128 x 128 */
    g_Rt[t*Dn + j] = rot[j*Dn + t];
    g_St[t*Dn + j] = S[j*Dn + t];

    if (blockIdx.x < BHn) {
        int bh = blockIdx.x;
        const float* qbase = query + (size_t)bh*SQn*Dn;
#pragma unroll
        for (int c = 0; c < (SQn*Dn)/128; ++c) {
            int o = t + c*128;
            int q = o >> 7, jj = o & 127;
            const float* qp = qbase + q*Dn;
            const float* rp = rot + jj*Dn;
            const float* sp = S   + jj*Dn;
            float aR = 0.f, aS = 0.f;
#pragma unroll 8
            for (int d = 0; d < Dn; ++d) {
                float qq = __ldg(qp + d);
                aR = __fmaf_rn(qq, __ldg(rp + d), aR);
                aS = __fmaf_rn(qq, __ldg(sp + d), aS);
            }
            g_qR[bh*SQn*Dn + o] = aR;
            g_qS[bh*SQn*Dn + o] = aS;
        }
    }
}

__device__ __forceinline__ float wsum(float v)
{
#pragma unroll
    for (int o = 16; o > 0; o >>= 1) v += __shfl_xor_sync(0xffffffffu, v, o);
    return v;
}

/* ---- packed f32x2 helpers (two independent IEEE fp32 ops each) ---- */
__device__ __forceinline__ u64 pk2(float lo, float hi)
{ u64 r; asm("mov.b64 %0,{%1,%2};" : "=l"(r) : "f"(lo), "f"(hi)); return r; }
__device__ __forceinline__ u64 dup2(float x)
{ u64 r; asm("mov.b64 %0,{%1,%1};" : "=l"(r) : "f"(x)); return r; }
__device__ __forceinline__ void fma2(u64& acc, u64 a, u64 b)
{ asm("fma.rn.f32x2 %0,%1,%2,%0;" : "+l"(acc) : "l"(a), "l"(b)); }
__device__ __forceinline__ float2 unpk(u64 v)
{ float2 f; asm("mov.b64 {%0,%1},%2;" : "=f"(f.x), "=f"(f.y) : "l"(v)); return f; }

/* ---- main fused kernel: one block = 128 keys of one (b,h), 8 warps,
   16 keys per warp (2 halves of 8 sharing each matrix load) ---- */
__global__ void __launch_bounds__(NTHREADS, 1)
turbo_main(const float* __restrict__ keys, const float* __restrict__ rot,
           const float* __restrict__ levels, float* __restrict__ out)
{
    __shared__ float  sM[Dn*Dn];        /* 64K: Rt -> rot -> St  */
    __shared__ float  sK[TILE*Dn];      /* 64K: keys -> k_hat -> r_hat */
    __shared__ float  sQR[SQn*Dn];      /*  8K */
    __shared__ float  sQS[SQn*Dn];      /*  8K */
    __shared__ float  sTab[256*4];      /*  4K: byte -> 4 level values */
    __shared__ float  sNorm[TILE];
    __shared__ float  sRn[TILE];
    __shared__ unsigned sSign[TILE*4];  /*  2K */
    __shared__ unsigned char sCodeB[TILE*32]; /* 4K: 2-bit yhat codes */

    const int tid = threadIdx.x, w = tid >> 5, lane = tid & 31;
    const int bh  = blockIdx.x >> 5;            /* 32 tiles per bh */
    const int k0  = (blockIdx.x & 31) * TILE;
    const float* keys_blk = keys + ((size_t)bh*SKn + k0)*Dn;

    const float L0 = __ldg(levels+0), L1 = __ldg(levels+1),
                L2 = __ldg(levels+2), L3 = __ldg(levels+3);
    const float bb0 = 0.5f*(L0+L1), bb1 = 0.5f*(L1+L2), bb2 = 0.5f*(L2+L3);

    /* cooperative loads */
    {
        const float4* g = (const float4*)keys_blk;
        float4* s = (float4*)sK;
#pragma unroll
        for (int i = tid; i < TILE*Dn/4; i += NTHREADS) s[i] = g[i];
    }
    {
        const float4* g = (const float4*)g_Rt; float4* s = (float4*)sM;
#pragma unroll
        for (int i = tid; i < Dn*Dn/4; i += NTHREADS) s[i] = g[i];
    }
    {
        const float4* g = (const float4*)(g_qR + bh*SQn*Dn); float4* s = (float4*)sQR;
#pragma unroll
        for (int i = tid; i < SQn*Dn/4; i += NTHREADS) s[i] = g[i];
        g = (const float4*)(g_qS + bh*SQn*Dn); s = (float4*)sQS;
#pragma unroll
        for (int i = tid; i < SQn*Dn/4; i += NTHREADS) s[i] = g[i];
    }
    /* byte -> float4 level decode table (exact level values) */
    {
        unsigned b = tid;
        float v[4];
#pragma unroll
        for (int c = 0; c < 4; ++c) {
            unsigned cc = (b >> (2*c)) & 3u;
            float lo = (cc & 1u) ? L1 : L0;
            float hi = (cc & 1u) ? L3 : L2;
            v[c] = (cc & 2u) ? hi : lo;
        }
        ((float4*)sTab)[b] = make_float4(v[0],v[1],v[2],v[3]);
    }
    __syncthreads();

    const int kb = w*16;

    /* norms (fp32, deterministic order); each warp owns 16 keys */
#pragma unroll
    for (int i = 0; i < 16; ++i) {
        int key = kb + i;
        float4 v = ((const float4*)(sK + key*Dn))[lane];
        float ss = __fmul_rn(v.x, v.x);
        ss = __fmaf_rn(v.y, v.y, ss);
        ss = __fmaf_rn(v.z, v.z, ss);
        ss = __fmaf_rn(v.w, v.w, ss);
        ss = wsum(ss);
        if (lane == 0) sNorm[key] = fmaxf(__fsqrt_rn(ss), 1e-8f);
    }
    __syncthreads();

    /* k_hat = fl(k / n) in place (IEEE div) */
#pragma unroll
    for (int i = tid; i < TILE*Dn; i += NTHREADS)
        sK[i] = __fdiv_rn(sK[i], sNorm[i >> 7]);
    __syncthreads();

    /* ===== phase 1: y = k_hat @ R^T (seq FMA over d); 2-bit codes ===== */
    {
        u64 axy[16], azw[16];
#pragma unroll
        for (int i = 0; i < 16; ++i) { axy[i] = 0ULL; azw[i] = 0ULL; }
        for (int db = 0; db < Dn; db += 4) {
            u64 rx[4], rz[4];
#pragma unroll
            for (int dd = 0; dd < 4; ++dd) {
                float4 r = ((const float4*)sM)[(db+dd)*32 + lane];
                rx[dd] = pk2(r.x, r.y); rz[dd] = pk2(r.z, r.w);
            }
#pragma unroll
            for (int h = 0; h < 2; ++h) {
                float xs[8][4];
#pragma unroll
                for (int i = 0; i < 8; ++i) {
                    float4 x = *(const float4*)(sK + (kb + h*8 + i)*Dn + db);
                    xs[i][0]=x.x; xs[i][1]=x.y; xs[i][2]=x.z; xs[i][3]=x.w;
                }
#pragma unroll
                for (int dd = 0; dd < 4; ++dd)
#pragma unroll
                    for (int i = 0; i < 8; ++i) {
                        u64 xx = dup2(xs[i][dd]);
                        fma2(axy[h*8+i], xx, rx[dd]);
                        fma2(azw[h*8+i], xx, rz[dd]);
                    }
            }
        }
#pragma unroll
        for (int i = 0; i < 16; ++i) {
            float2 lo = unpk(axy[i]), hi = unpk(azw[i]);
            unsigned c0, c1, c2, c3;
            { float y = lo.x; c0 = (unsigned)(y > bb0) + (unsigned)(y > bb1) + (unsigned)(y > bb2); }
            { float y = lo.y; c1 = (unsigned)(y > bb0) + (unsigned)(y > bb1) + (unsigned)(y > bb2); }
            { float y = hi.x; c2 = (unsigned)(y > bb0) + (unsigned)(y > bb1) + (unsigned)(y > bb2); }
            { float y = hi.y; c3 = (unsigned)(y > bb0) + (unsigned)(y > bb1) + (unsigned)(y > bb2); }
            sCodeB[(kb+i)*32 + lane] = (unsigned char)(c0 | (c1<<2) | (c2<<4) | (c3<<6));
        }
    }
    __syncthreads();

    /* reload matrix slot with R itself (row-major rot[j][d]) */
    {
        const float4* g = (const float4*)rot; float4* s = (float4*)sM;
#pragma unroll
        for (int i = tid; i < Dn*Dn/4; i += NTHREADS) s[i] = g[i];
    }
    __syncthreads();

    /* ===== phase 2: keys_mse = fl(fl(yhat@R)*n); residual; r_hat ===== */
    {
        u64 axy[16], azw[16];
#pragma unroll
        for (int i = 0; i < 16; ++i) { axy[i] = 0ULL; azw[i] = 0ULL; }
        for (int g = 0; g < 32; ++g) {          /* j = 4g..4g+3 */
            u64 rx[4], rz[4];
#pragma unroll
            for (int dd = 0; dd < 4; ++dd) {
                float4 r = ((const float4*)sM)[(4*g+dd)*32 + lane];
                rx[dd] = pk2(r.x, r.y); rz[dd] = pk2(r.z, r.w);
            }
#pragma unroll
            for (int h = 0; h < 2; ++h) {
                float xs[8][4];
#pragma unroll
                for (int i = 0; i < 8; ++i) {
                    float4 x = ((const float4*)sTab)[sCodeB[(kb + h*8 + i)*32 + g]];
                    xs[i][0]=x.x; xs[i][1]=x.y; xs[i][2]=x.z; xs[i][3]=x.w;
                }
#pragma unroll
                for (int dd = 0; dd < 4; ++dd)
#pragma unroll
                    for (int i = 0; i < 8; ++i) {
                        u64 xx = dup2(xs[i][dd]);
                        fma2(axy[h*8+i], xx, rx[dd]);
                        fma2(azw[h*8+i], xx, rz[dd]);
                    }
            }
        }
#pragma unroll
        for (int i = 0; i < 16; ++i) {
            int key = kb + i;
            float n = sNorm[key];
            float2 lo = unpk(axy[i]), hi = unpk(azw[i]);
            float4 kg = ((const float4*)(keys_blk + (size_t)key*Dn))[lane];
            float4 r;
            r.x = __fadd_rn(kg.x, -__fmul_rn(lo.x, n));
            r.y = __fadd_rn(kg.y, -__fmul_rn(lo.y, n));
            r.z = __fadd_rn(kg.z, -__fmul_rn(hi.x, n));
            r.w = __fadd_rn(kg.w, -__fmul_rn(hi.y, n));
            float ss = __fmul_rn(r.x, r.x);
            ss = __fmaf_rn(r.y, r.y, ss);
            ss = __fmaf_rn(r.z, r.z, ss);
            ss = __fmaf_rn(r.w, r.w, ss);
            ss = wsum(ss);
            float rn = fmaxf(__fsqrt_rn(ss), 1e-10f);
            if (lane == 0) sRn[key] = rn;
            float4 rh;
            rh.x = __fdiv_rn(r.x, rn);
            rh.y = __fdiv_rn(r.y, rn);
            rh.z = __fdiv_rn(r.z, rn);
            rh.w = __fdiv_rn(r.w, rn);
            ((float4*)(sK + key*Dn))[lane] = rh;   /* k_hat -> r_hat */
        }
    }
    __syncthreads();

    /* reload matrix slot: St[d][m] */
    {
        const float4* g = (const float4*)g_St; float4* s = (float4*)sM;
#pragma unroll
        for (int i = tid; i < Dn*Dn/4; i += NTHREADS) s[i] = g[i];
    }
    __syncthreads();

    /* ===== phase 3: proj = r_hat @ S^T (seq FMA over d); signs ===== */
    {
        u64 axy[16], azw[16];
#pragma unroll
        for (int i = 0; i < 16; ++i) { axy[i] = 0ULL; azw[i] = 0ULL; }
        for (int db = 0; db < Dn; db += 4) {
            u64 rx[4], rz[4];
#pragma unroll
            for (int dd = 0; dd < 4; ++dd) {
                float4 r = ((const float4*)sM)[(db+dd)*32 + lane];
                rx[dd] = pk2(r.x, r.y); rz[dd] = pk2(r.z, r.w);
            }
#pragma unroll
            for (int h = 0; h < 2; ++h) {
                float xs[8][4];
#pragma unroll
                for (int i = 0; i < 8; ++i) {
                    float4 x = *(const float4*)(sK + (kb + h*8 + i)*Dn + db);
                    xs[i][0]=x.x; xs[i][1]=x.y; xs[i][2]=x.z; xs[i][3]=x.w;
                }
#pragma unroll
                for (int dd = 0; dd < 4; ++dd)
#pragma unroll
                    for (int i = 0; i < 8; ++i) {
                        u64 xx = dup2(xs[i][dd]);
                        fma2(axy[h*8+i], xx, rx[dd]);
                        fma2(azw[h*8+i], xx, rz[dd]);
                    }
            }
        }
#pragma unroll
        for (int i = 0; i < 16; ++i) {
            float2 lo = unpk(axy[i]), hi = unpk(azw[i]);
            unsigned b0 = __ballot_sync(0xffffffffu, lo.x >= 0.f);
            unsigned b1 = __ballot_sync(0xffffffffu, lo.y >= 0.f);
            unsigned b2 = __ballot_sync(0xffffffffu, hi.x >= 0.f);
            unsigned b3 = __ballot_sync(0xffffffffu, hi.y >= 0.f);
            if (lane == 0) {
                unsigned* sp = sSign + (size_t)(kb+i)*4;
                sp[0]=b0; sp[1]=b1; sp[2]=b2; sp[3]=b3;
            }
        }
    }
    __syncthreads();

    /* ===== epilogue (shfl-free): warp -> 2 q rows, lane -> 4 keys ===== */
    {
        const float cq = 0.0097915167f;   /* sqrt(pi/2)/128 */
        const int q0 = 2*w, q1 = 2*w + 1;
        const float* qr0 = sQR + q0*Dn;
        const float* qr1 = sQR + q1*Dn;
        const float* qs0 = sQS + q0*Dn;
        const float* qs1 = sQS + q1*Dn;
        float* og = out + ((size_t)bh*SQn)*SKn + k0;

#pragma unroll
        for (int kc = 0; kc < 4; ++kc) {        /* key columns lane + 32*kc */
            const int key = lane + 32*kc;
            const unsigned char* cK = sCodeB + key*32;
            float e0 = 0.f, e1 = 0.f;
#pragma unroll 4
            for (int g = 0; g < 32; ++g) {
                float4 a0 = ((const float4*)qr0)[g];
                float4 a1 = ((const float4*)qr1)[g];
                float4 yv = ((const float4*)sTab)[cK[g]];
                e0 = __fmaf_rn(a0.x, yv.x, e0); e0 = __fmaf_rn(a0.y, yv.y, e0);
                e0 = __fmaf_rn(a0.z, yv.z, e0); e0 = __fmaf_rn(a0.w, yv.w, e0);
                e1 = __fmaf_rn(a1.x, yv.x, e1); e1 = __fmaf_rn(a1.y, yv.y, e1);
                e1 = __fmaf_rn(a1.z, yv.z, e1); e1 = __fmaf_rn(a1.w, yv.w, e1);
            }
            unsigned w0 = sSign[key*4+0], w1 = sSign[key*4+1],
                     w2 = sSign[key*4+2], w3 = sSign[key*4+3];
            float s0 = 0.f, s1 = 0.f;
#pragma unroll 4
            for (int g = 0; g < 32; ++g) {      /* m = 4g + c, bit g of word c */
                float4 b0 = ((const float4*)qs0)[g];
                float4 b1 = ((const float4*)qs1)[g];
                float f0 = ((w0 >> g) & 1u) ? 1.f : -1.f;
                float f1 = ((w1 >> g) & 1u) ? 1.f : -1.f;
                float f2 = ((w2 >> g) & 1u) ? 1.f : -1.f;
                float f3 = ((w3 >> g) & 1u) ? 1.f : -1.f;
                s0 = __fmaf_rn(f0, b0.x, s0); s0 = __fmaf_rn(f1, b0.y, s0);
                s0 = __fmaf_rn(f2, b0.z, s0); s0 = __fmaf_rn(f3, b0.w, s0);
                s1 = __fmaf_rn(f0, b1.x, s1); s1 = __fmaf_rn(f1, b1.y, s1);
                s1 = __fmaf_rn(f2, b1.z, s1); s1 = __fmaf_rn(f3, b1.w, s1);
            }
            float n = sNorm[key], g2 = cq * sRn[key];
            og[(size_t)q0*SKn + key] = n*e0 + g2*s0;
            og[(size_t)q1*SKn + key] = n*e1 + g2*s1;
        }
    }
}

extern "C" void kernel_launch(void* const* d_in, const int* in_sizes, int n_in,
                              void* d_out, int out_size)
{
    const float* query  = (const float*)d_in[0];
    const float* keys   = (const float*)d_in[1];
    const float* rot    = (const float*)d_in[2];
    const float* S      = (const float*)d_in[3];
    const float* levels = (const float*)d_in[4];
    float* out = (float*)d_out;

    prep_all<<<Dn, Dn>>>(query, rot, S);
    turbo_main<<<NBLOCKS, NTHREADS>>>(keys, rot, levels, out);
}